// round 1
// baseline (speedup 1.0000x reference)
#include <cuda_runtime.h>
#include <cuda_bf16.h>
#include <cstdint>
#include <cstddef>

// Problem constants
#define NB    32768
#define HID   512
#define KMID  264     // key/sp mid dim
#define DMID  384     // dec mid dim
#define DIM   256
#define MAXN  17
#define TMAX  (NB * 16)   // 524288 worst-case tokens

// ---------------- static device scratch (no dynamic allocation) ----------------
__device__ __align__(16) float g_keys[MAXN * HID];          // 17x512 precomputed key rows
__device__ __align__(16) float g_U[(size_t)NB * KMID];      // z @ sp_W1 + b   (34.6 MB)
__device__ int   g_n[NB];
__device__ int   g_off[NB];
__device__ int   g_total;
__device__ int   g_tok_b[TMAX];
__device__ unsigned char g_tok_k[TMAX];
__device__ __align__(16) float g_H[(size_t)TMAX * DMID];    // decoder hidden (805 MB worst case)

// ---------------- kernel 1: precompute 17 key rows ----------------
// keys[k] = relu(LN(key_W1[k,:] + key_b1, g, be)) @ key_W2 + key_b2
__global__ void keys_kernel(const float* __restrict__ kW1, const float* __restrict__ kb1,
                            const float* __restrict__ kg1, const float* __restrict__ kbe1,
                            const float* __restrict__ kW2, const float* __restrict__ kb2)
{
    int k = blockIdx.x;
    __shared__ float h[KMID];
    __shared__ float red[18];
    int t = threadIdx.x;   // 256 threads
    float s = 0.f, sq = 0.f;
    for (int j = t; j < KMID; j += 256) {
        float u = kW1[k * KMID + j] + kb1[j];
        h[j] = u;
        s += u; sq += u * u;
    }
    // warp reduce
    for (int d = 16; d; d >>= 1) { s += __shfl_xor_sync(~0u, s, d); sq += __shfl_xor_sync(~0u, sq, d); }
    if ((t & 31) == 0) { red[t >> 5] = s; red[8 + (t >> 5)] = sq; }
    __syncthreads();
    if (t == 0) {
        float S = 0.f, SQ = 0.f;
        for (int i = 0; i < 8; i++) { S += red[i]; SQ += red[8 + i]; }
        red[16] = S; red[17] = SQ;
    }
    __syncthreads();
    float mean = red[16] * (1.f / KMID);
    float var  = red[17] * (1.f / KMID) - mean * mean;
    float inv  = rsqrtf(var + 1e-5f);
    for (int j = t; j < KMID; j += 256)
        h[j] = fmaxf((h[j] - mean) * inv * kg1[j] + kbe1[j], 0.f);
    __syncthreads();
    for (int c = t; c < HID; c += 256) {
        float acc = kb2[c];
        #pragma unroll 4
        for (int j = 0; j < KMID; j++) acc += h[j] * kW2[(size_t)j * HID + c];
        g_keys[k * HID + c] = acc;
    }
}

// ---------------- generic fp32 GEMM: C = op(A) @ W + bias ----------------
// AMODE: 0 = A param (row-major MxK)
//        1 = gathered+scaled: A[t,:] = z[tok_b[t],:] * g_keys[tok_k[t],:]   (M = g_total)
//        2 = A = g_H                                                        (M = g_total)
// CSEL:  0 = C param, 1 = g_U, 2 = g_H
#define BM 128
#define BN 64
#define BK 16

template<int AMODE, int CSEL, int RELU>
__global__ void __launch_bounds__(128)
gemm_kernel(const float* __restrict__ Ag, const float* __restrict__ Wg,
            const float* __restrict__ bias, float* __restrict__ Cg,
            int M, int N, int K, int ldc)
{
    int Meff = (AMODE == 0) ? M : g_total;
    int row0 = blockIdx.y * BM;
    if (row0 >= Meff) return;
    int col0 = blockIdx.x * BN;

    __shared__ float As[BK][BM];
    __shared__ float Bs[BK][BN];

    int tid = threadIdx.x;            // 128 threads; thread tid loads A-row row0+tid
    int r  = row0 + tid;
    int rs = (r < Meff) ? r : (Meff - 1);
    const float* arow;
    const float* krow = nullptr;
    if (AMODE == 0)      arow = Ag + (size_t)rs * K;
    else if (AMODE == 1) { arow = Ag + (size_t)g_tok_b[rs] * K; krow = g_keys + (int)g_tok_k[rs] * HID; }
    else                 arow = g_H + (size_t)rs * K;

    float acc[8][8];
    #pragma unroll
    for (int i = 0; i < 8; i++)
        #pragma unroll
        for (int j = 0; j < 8; j++) acc[i][j] = 0.f;

    int tr  = tid & 15;   // row group: rows tr*8 .. tr*8+7
    int tcg = tid >> 4;   // col group: cols tcg*8 .. tcg*8+7

    for (int k0 = 0; k0 < K; k0 += BK) {
        // load A: 16 consecutive floats of this thread's row (vectorized)
        #pragma unroll
        for (int i = 0; i < BK; i += 4) {
            float4 v = *(const float4*)(arow + k0 + i);
            if (AMODE == 1) {
                float4 kv = *(const float4*)(krow + k0 + i);
                v.x *= kv.x; v.y *= kv.y; v.z *= kv.z; v.w *= kv.w;
            }
            As[i + 0][tid] = v.x; As[i + 1][tid] = v.y;
            As[i + 2][tid] = v.z; As[i + 3][tid] = v.w;
        }
        // load B: 16x64 tile, coalesced, bounds-masked on N
        #pragma unroll
        for (int i = 0; i < 8; i++) {
            int e  = tid + 128 * i;
            int br = e >> 6;        // /64
            int bc = e & 63;
            int col = col0 + bc;
            Bs[br][bc] = (col < N) ? Wg[(size_t)(k0 + br) * N + col] : 0.f;
        }
        __syncthreads();
        #pragma unroll
        for (int k = 0; k < BK; k++) {
            float a[8], b[8];
            #pragma unroll
            for (int i = 0; i < 8; i++) a[i] = As[k][tr * 8 + i];
            #pragma unroll
            for (int j = 0; j < 8; j++) b[j] = Bs[k][tcg * 8 + j];
            #pragma unroll
            for (int i = 0; i < 8; i++)
                #pragma unroll
                for (int j = 0; j < 8; j++)
                    acc[i][j] = fmaf(a[i], b[j], acc[i][j]);
        }
        __syncthreads();
    }

    float* dst = (CSEL == 0) ? Cg : (CSEL == 1 ? g_U : g_H);
    #pragma unroll
    for (int i = 0; i < 8; i++) {
        int row = row0 + tr * 8 + i;
        if (row >= Meff) continue;
        #pragma unroll
        for (int j = 0; j < 8; j++) {
            int col = col0 + tcg * 8 + j;
            if (col >= N) continue;
            float v = acc[i][j] + bias[col];
            if (RELU) v = fmaxf(v, 0.f);
            dst[(size_t)row * ldc + col] = v;
        }
    }
}

// ---------------- size-pred epilogue: LN + relu + @sp_W2 + argmax -> g_n ----------------
__global__ void sizepred_kernel(const float* __restrict__ W2, const float* __restrict__ b2,
                                const float* __restrict__ g1, const float* __restrict__ be1)
{
    int w = (blockIdx.x * blockDim.x + threadIdx.x) >> 5;
    int lane = threadIdx.x & 31;
    if (w >= NB) return;
    const float* u = g_U + (size_t)w * KMID;
    float vals[9];
    float s = 0.f, sq = 0.f;
    #pragma unroll
    for (int i = 0; i < 9; i++) {
        int j = lane + 32 * i;
        float v = (j < KMID) ? u[j] : 0.f;
        vals[i] = v; s += v; sq += v * v;
    }
    for (int d = 16; d; d >>= 1) { s += __shfl_xor_sync(~0u, s, d); sq += __shfl_xor_sync(~0u, sq, d); }
    float mean = s * (1.f / KMID);
    float var  = sq * (1.f / KMID) - mean * mean;
    float inv  = rsqrtf(var + 1e-5f);
    float logit[MAXN];
    #pragma unroll
    for (int o = 0; o < MAXN; o++) logit[o] = 0.f;
    #pragma unroll
    for (int i = 0; i < 9; i++) {
        int j = lane + 32 * i;
        if (j < KMID) {
            float h = fmaxf((vals[i] - mean) * inv * g1[j] + be1[j], 0.f);
            #pragma unroll
            for (int o = 0; o < MAXN; o++) logit[o] += h * W2[j * MAXN + o];
        }
    }
    #pragma unroll
    for (int o = 0; o < MAXN; o++)
        for (int d = 16; d; d >>= 1) logit[o] += __shfl_xor_sync(~0u, logit[o], d);
    if (lane == 0) {
        float best = -1e30f; int bi = 0;
        #pragma unroll
        for (int o = 0; o < MAXN; o++) {
            float v = logit[o] + b2[o];
            if (v > best) { best = v; bi = o; }   // strict > keeps first max (jnp.argmax semantics)
        }
        g_n[w] = bi;
    }
}

// ---------------- single-block exclusive scan over g_n (32768 = 1024 threads x 32) ----------------
__global__ void scan_kernel()
{
    __shared__ int part[1024];
    int t = threadIdx.x;
    int base = t * 32;
    int loc[32];
    int s = 0;
    #pragma unroll
    for (int i = 0; i < 32; i++) { int v = g_n[base + i]; loc[i] = s; s += v; }
    part[t] = s;
    __syncthreads();
    for (int d = 1; d < 1024; d <<= 1) {
        int v = (t >= d) ? part[t - d] : 0;
        __syncthreads();
        part[t] += v;
        __syncthreads();
    }
    int exc = part[t] - s;
    #pragma unroll
    for (int i = 0; i < 32; i++) g_off[base + i] = exc + loc[i];
    if (t == 1023) g_total = part[1023];
}

// ---------------- build token map ----------------
__global__ void tokmap_kernel()
{
    int b = blockIdx.x * 256 + threadIdx.x;
    if (b >= NB) return;
    int off = g_off[b], n = g_n[b];
    for (int j = 0; j < n; j++) { g_tok_b[off + j] = b; g_tok_k[off + j] = (unsigned char)j; }
}

// ---------------- optional second output: batch ids as float, if the buffer expects them ----------------
__global__ void batchout_kernel(float* __restrict__ out, long long out_size)
{
    int t = blockIdx.x * 256 + threadIdx.x;
    int total = g_total;
    if ((long long)total * 257 > out_size) return;   // output buffer holds x only
    if (t < total) out[(long long)total * 256 + t] = (float)g_tok_b[t];
}

// ---------------- launch ----------------
extern "C" void kernel_launch(void* const* d_in, const int* in_sizes, int n_in,
                              void* d_out, int out_size)
{
    const float* z     = (const float*)d_in[0];
    const float* kW1   = (const float*)d_in[1];
    const float* kb1   = (const float*)d_in[2];
    const float* kg1   = (const float*)d_in[3];
    const float* kbe1  = (const float*)d_in[4];
    const float* kW2   = (const float*)d_in[5];
    const float* kb2   = (const float*)d_in[6];
    const float* dW1   = (const float*)d_in[7];
    const float* db1   = (const float*)d_in[8];
    const float* dW2   = (const float*)d_in[9];
    const float* db2   = (const float*)d_in[10];
    const float* spW1  = (const float*)d_in[11];
    const float* spb1  = (const float*)d_in[12];
    const float* spg1  = (const float*)d_in[13];
    const float* spbe1 = (const float*)d_in[14];
    const float* spW2  = (const float*)d_in[15];
    const float* spb2  = (const float*)d_in[16];
    float* out = (float*)d_out;

    // 1. 17 key rows
    keys_kernel<<<17, 256>>>(kW1, kb1, kg1, kbe1, kW2, kb2);

    // 2. U = z @ sp_W1 + sp_b1   [32768 x 264]
    gemm_kernel<0, 1, 0><<<dim3((KMID + BN - 1) / BN, NB / BM), 128>>>(
        z, spW1, spb1, nullptr, NB, KMID, HID, KMID);

    // 3. LN/relu/sp_W2/argmax -> g_n
    sizepred_kernel<<<(NB * 32) / 256, 256>>>(spW2, spb2, spg1, spbe1);

    // 4. prefix sum -> g_off, g_total
    scan_kernel<<<1, 1024>>>();

    // 5. token map
    tokmap_kernel<<<NB / 256, 256>>>();

    // 6. H = relu((z[b] * keys[k]) @ dec_W1 + b1)   [T x 384], grid sized for T_max
    gemm_kernel<1, 2, 1><<<dim3(DMID / BN, TMAX / BM), 128>>>(
        z, dW1, db1, nullptr, 0, DMID, HID, DMID);

    // 7. x = H @ dec_W2 + b2 -> d_out   [T x 256]
    gemm_kernel<2, 0, 0><<<dim3(DIM / BN, TMAX / BM), 128>>>(
        nullptr, dW2, db2, out, 0, DIM, DMID, DIM);

    // 8. batch ids (only if the output buffer holds both x and batch)
    batchout_kernel<<<TMAX / 256, 256>>>(out, (long long)out_size);
}

// round 3
// speedup vs baseline: 2.2869x; 2.2869x over previous
#include <cuda_runtime.h>
#include <cuda_bf16.h>
#include <cstdint>
#include <cstddef>

// Problem constants
#define NB    32768
#define HID   512
#define KMID  264
#define DMID  384
#define DIM   256
#define MAXN  17
#define TMAX  (NB * 16)   // 524288 worst-case tokens

// ---------------- static device scratch ----------------
__device__ __align__(16) float g_keys[MAXN * HID];
__device__ __align__(16) float g_U[(size_t)NB * KMID];
__device__ int   g_n[NB];
__device__ int   g_off[NB];
__device__ int   g_total;
__device__ int   g_tok_b[TMAX];
__device__ unsigned char g_tok_k[TMAX];
__device__ __align__(16) float g_H[(size_t)TMAX * DMID];

// pre-split bf16 weights in HMMA-friendly layout:
// element (chunk c, col n, k-local kl) at offset BOFF + (c*N + n)*72 + kl
#define B1_ELEMS (8 * DMID * 72)    // 221184
#define B2_ELEMS (6 * DIM * 72)     // 110592
#define B1_OFF 0
#define B2_OFF B1_ELEMS
__device__ __align__(16) __nv_bfloat16 g_Bh[B1_ELEMS + B2_ELEMS];
__device__ __align__(16) __nv_bfloat16 g_Bl[B1_ELEMS + B2_ELEMS];

__device__ __forceinline__ uint32_t smem_u32(const void* p) {
    uint32_t a;
    asm("{ .reg .u64 t; cvta.to.shared.u64 t, %1; cvt.u32.u64 %0, t; }" : "=r"(a) : "l"(p));
    return a;
}

// ---------------- weight prep: W[K,N] fp32 -> hi/lo bf16, [c][n][kl] stride-72 ----------------
template<int BOFF>
__global__ void prep_kernel(const float* __restrict__ W, int K, int N)
{
    int t = blockIdx.x * 256 + threadIdx.x;
    int total = N * (K / 8);
    if (t >= total) return;
    int n  = t / (K / 8);
    int k0 = (t % (K / 8)) * 8;
    unsigned short hb[8], lb[8];
    #pragma unroll
    for (int j = 0; j < 8; j++) {
        float v = W[(size_t)(k0 + j) * N + n];
        __nv_bfloat16 h = __float2bfloat16(v);
        __nv_bfloat16 l = __float2bfloat16(v - __bfloat162float(h));
        hb[j] = __bfloat16_as_ushort(h);
        lb[j] = __bfloat16_as_ushort(l);
    }
    uint4 hv, lv;
    hv.x = hb[0] | ((uint32_t)hb[1] << 16); hv.y = hb[2] | ((uint32_t)hb[3] << 16);
    hv.z = hb[4] | ((uint32_t)hb[5] << 16); hv.w = hb[6] | ((uint32_t)hb[7] << 16);
    lv.x = lb[0] | ((uint32_t)lb[1] << 16); lv.y = lb[2] | ((uint32_t)lb[3] << 16);
    lv.z = lb[4] | ((uint32_t)lb[5] << 16); lv.w = lb[6] | ((uint32_t)lb[7] << 16);
    int c  = k0 / 64;
    int kl = k0 % 64;
    size_t boff = ((size_t)BOFF + ((size_t)c * N + n) * 72 + kl) * 2;
    *(uint4*)((char*)g_Bh + boff) = hv;
    *(uint4*)((char*)g_Bl + boff) = lv;
}

// ---------------- keys precompute (17 rows) ----------------
__global__ void keys_kernel(const float* __restrict__ kW1, const float* __restrict__ kb1,
                            const float* __restrict__ kg1, const float* __restrict__ kbe1,
                            const float* __restrict__ kW2, const float* __restrict__ kb2)
{
    int k = blockIdx.x;
    __shared__ float h[KMID];
    __shared__ float red[18];
    int t = threadIdx.x;
    float s = 0.f, sq = 0.f;
    for (int j = t; j < KMID; j += 256) {
        float u = kW1[k * KMID + j] + kb1[j];
        h[j] = u; s += u; sq += u * u;
    }
    for (int d = 16; d; d >>= 1) { s += __shfl_xor_sync(~0u, s, d); sq += __shfl_xor_sync(~0u, sq, d); }
    if ((t & 31) == 0) { red[t >> 5] = s; red[8 + (t >> 5)] = sq; }
    __syncthreads();
    if (t == 0) {
        float S = 0.f, SQ = 0.f;
        for (int i = 0; i < 8; i++) { S += red[i]; SQ += red[8 + i]; }
        red[16] = S; red[17] = SQ;
    }
    __syncthreads();
    float mean = red[16] * (1.f / KMID);
    float var  = red[17] * (1.f / KMID) - mean * mean;
    float inv  = rsqrtf(var + 1e-5f);
    for (int j = t; j < KMID; j += 256)
        h[j] = fmaxf((h[j] - mean) * inv * kg1[j] + kbe1[j], 0.f);
    __syncthreads();
    for (int c = t; c < HID; c += 256) {
        float acc = kb2[c];
        #pragma unroll 4
        for (int j = 0; j < KMID; j++) acc += h[j] * kW2[(size_t)j * HID + c];
        g_keys[k * HID + c] = acc;
    }
}

// ---------------- fp32 SIMT GEMM for the size-pred path (argmax must be bit-safe) ----------------
#define BM 128
#define BN 64
#define BK 16
__global__ void __launch_bounds__(128)
gemm32_sp(const float* __restrict__ Ag, const float* __restrict__ Wg,
          const float* __restrict__ bias)
{
    const int M = NB, N = KMID, K = HID;
    int row0 = blockIdx.y * BM;
    int col0 = blockIdx.x * BN;

    __shared__ float As[BK][BM];
    __shared__ float Bs[BK][BN];

    int tid = threadIdx.x;
    const float* arow = Ag + (size_t)(row0 + tid) * K;

    float acc[8][8];
    #pragma unroll
    for (int i = 0; i < 8; i++)
        #pragma unroll
        for (int j = 0; j < 8; j++) acc[i][j] = 0.f;

    int tr  = tid & 15;
    int tcg = tid >> 4;

    for (int k0 = 0; k0 < K; k0 += BK) {
        #pragma unroll
        for (int i = 0; i < BK; i += 4) {
            float4 v = *(const float4*)(arow + k0 + i);
            As[i + 0][tid] = v.x; As[i + 1][tid] = v.y;
            As[i + 2][tid] = v.z; As[i + 3][tid] = v.w;
        }
        #pragma unroll
        for (int i = 0; i < 8; i++) {
            int e  = tid + 128 * i;
            int br = e >> 6;
            int bc = e & 63;
            int col = col0 + bc;
            Bs[br][bc] = (col < N) ? Wg[(size_t)(k0 + br) * N + col] : 0.f;
        }
        __syncthreads();
        #pragma unroll
        for (int k = 0; k < BK; k++) {
            float a[8], b[8];
            #pragma unroll
            for (int i = 0; i < 8; i++) a[i] = As[k][tr * 8 + i];
            #pragma unroll
            for (int j = 0; j < 8; j++) b[j] = Bs[k][tcg * 8 + j];
            #pragma unroll
            for (int i = 0; i < 8; i++)
                #pragma unroll
                for (int j = 0; j < 8; j++)
                    acc[i][j] = fmaf(a[i], b[j], acc[i][j]);
        }
        __syncthreads();
    }
    #pragma unroll
    for (int i = 0; i < 8; i++) {
        int row = row0 + tr * 8 + i;
        #pragma unroll
        for (int j = 0; j < 8; j++) {
            int col = col0 + tcg * 8 + j;
            if (col < N) g_U[(size_t)row * N + col] = acc[i][j] + bias[col];
        }
    }
}

// ---------------- split-bf16 HMMA GEMM (mma.sync m16n8k16) ----------------
// AMODE: 1 = A[t,:] = z[tok_b[t],:]*g_keys[tok_k[t],:]   2 = A = g_H
// DST:   0 = Cg param, 2 = g_H
// CTA tile 128x128, 8 warps (warp tile 32x64), K chunks of 64, double-buffered.
#define STG_BYTES 73728        // per stage: (Ah+Al+Bh+Bl) * 128*72*2B
#define AH_OFF 0
#define AL_OFF 18432
#define BH_OFF 36864
#define BL_OFF 55296

template<int AMODE, int NTOT, int KTOT, int RELU, int DST, int BOFF>
__global__ void __launch_bounds__(256, 1)
hmma_gemm(const float* __restrict__ Ag, const float* __restrict__ bias, float* __restrict__ Cg)
{
    constexpr int NC = KTOT / 64;
    int Meff = g_total;
    int row0 = blockIdx.x * 128;
    if (row0 >= Meff) return;
    int n0 = blockIdx.y * 128;

    extern __shared__ char dyn[];
    __shared__ int s_tb[128];
    __shared__ unsigned char s_tk[128];

    int tid  = threadIdx.x;
    int wid  = tid >> 5;
    int lane = tid & 31;
    int warp_m = wid & 3;        // 4 row groups of 32
    int warp_n = wid >> 2;       // 2 col groups of 64

    if (AMODE == 1 && tid < 128) {
        int r = min(row0 + tid, Meff - 1);
        s_tb[tid] = g_tok_b[r];
        s_tk[tid] = g_tok_k[r];
    }
    __syncthreads();

    // per-thread A prefetch mapping: 8 float4 segs; row fixed across chunks
    int seg    = tid & 15;       // k-offset seg*4 within chunk
    int rbase  = tid >> 4;       // rows rbase + 16*i
    float4 apre[8];

    const uint32_t dynb = smem_u32(dyn);

    // ---- helpers as lambdas ----
    auto loadA = [&](int c) {
        int kg = c * 64 + seg * 4;
        #pragma unroll
        for (int i = 0; i < 8; i++) {
            int rl = rbase + 16 * i;
            if (AMODE == 1) {
                const float* zr = Ag + (size_t)s_tb[rl] * HID + kg;
                const float* kr = g_keys + (int)s_tk[rl] * HID + kg;
                float4 a = *(const float4*)zr;
                float4 k = *(const float4*)kr;
                a.x *= k.x; a.y *= k.y; a.z *= k.z; a.w *= k.w;
                apre[i] = a;
            } else {
                int r = min(row0 + rl, Meff - 1);
                apre[i] = *(const float4*)(g_H + (size_t)r * KTOT + kg);
            }
        }
    };
    auto stsA = [&](int stage) {
        char* base = dyn + stage * STG_BYTES;
        #pragma unroll
        for (int i = 0; i < 8; i++) {
            int rl = rbase + 16 * i;
            float f[4] = {apre[i].x, apre[i].y, apre[i].z, apre[i].w};
            uint32_t h2[2], l2[2];
            #pragma unroll
            for (int q = 0; q < 2; q++) {
                unsigned short hh[2], ll[2];
                #pragma unroll
                for (int j = 0; j < 2; j++) {
                    float v = f[q * 2 + j];
                    __nv_bfloat16 h = __float2bfloat16(v);
                    __nv_bfloat16 l = __float2bfloat16(v - __bfloat162float(h));
                    hh[j] = __bfloat16_as_ushort(h);
                    ll[j] = __bfloat16_as_ushort(l);
                }
                h2[q] = hh[0] | ((uint32_t)hh[1] << 16);
                l2[q] = ll[0] | ((uint32_t)ll[1] << 16);
            }
            size_t off = (size_t)rl * 144 + seg * 8;
            *(uint2*)(base + AH_OFF + off) = make_uint2(h2[0], h2[1]);
            *(uint2*)(base + AL_OFF + off) = make_uint2(l2[0], l2[1]);
        }
    };
    auto cpB = [&](int c, int stage) {
        // 128 rows x 9 x 16B, hi & lo
        uint32_t dsth = dynb + stage * STG_BYTES + BH_OFF;
        uint32_t dstl = dynb + stage * STG_BYTES + BL_OFF;
        const char* srch = (const char*)g_Bh + ((size_t)BOFF + ((size_t)c * NTOT + n0) * 72) * 2;
        const char* srcl = (const char*)g_Bl + ((size_t)BOFF + ((size_t)c * NTOT + n0) * 72) * 2;
        #pragma unroll
        for (int it = 0; it < 5; it++) {
            int tt = tid + 256 * it;
            if (tt < 128 * 9) {
                int row = tt / 9, sg = tt - row * 9;
                uint32_t o = row * 144 + sg * 16;
                asm volatile("cp.async.cg.shared.global [%0], [%1], 16;" ::
                             "r"(dsth + o), "l"(srch + o));
                asm volatile("cp.async.cg.shared.global [%0], [%1], 16;" ::
                             "r"(dstl + o), "l"(srcl + o));
            }
        }
        asm volatile("cp.async.commit_group;");
    };

    float acc[2][8][4];
    #pragma unroll
    for (int mi = 0; mi < 2; mi++)
        #pragma unroll
        for (int fj = 0; fj < 8; fj++)
            #pragma unroll
            for (int q = 0; q < 4; q++) acc[mi][fj][q] = 0.f;

    // ldmatrix lane-invariant offsets (bytes)
    uint32_t a_off = (uint32_t)(warp_m * 32 + (lane & 15)) * 144 + ((lane >> 4) << 3) * 2;
    uint32_t b_off = (uint32_t)(warp_n * 64 + (lane & 7) + ((lane >> 4) << 3)) * 144
                   + (((lane >> 3) & 1) << 3) * 2;

    // prologue
    loadA(0);
    cpB(0, 0);
    stsA(0);
    asm volatile("cp.async.wait_group 0;");
    __syncthreads();

    for (int c = 0; c < NC; c++) {
        int stage = c & 1;
        if (c + 1 < NC) { loadA(c + 1); cpB(c + 1, stage ^ 1); }

        uint32_t sb = dynb + stage * STG_BYTES;
        #pragma unroll
        for (int p = 0; p < 3; p++) {
            uint32_t Ab = sb + (p == 2 ? AL_OFF : AH_OFF) + a_off;
            uint32_t Bb = sb + (p == 1 ? BL_OFF : BH_OFF) + b_off;
            #pragma unroll
            for (int k16 = 0; k16 < 4; k16++) {
                uint32_t kb = (uint32_t)k16 * 32;   // 16 elems * 2B
                uint32_t af[2][4];
                #pragma unroll
                for (int mi = 0; mi < 2; mi++) {
                    uint32_t addr = Ab + mi * 2304 + kb;   // 16*144
                    asm volatile("ldmatrix.sync.aligned.m8n8.x4.shared.b16 {%0,%1,%2,%3}, [%4];"
                        : "=r"(af[mi][0]), "=r"(af[mi][1]), "=r"(af[mi][2]), "=r"(af[mi][3])
                        : "r"(addr));
                }
                uint32_t bf[4][4];
                #pragma unroll
                for (int gj = 0; gj < 4; gj++) {
                    uint32_t addr = Bb + gj * 2304 + kb;
                    asm volatile("ldmatrix.sync.aligned.m8n8.x4.shared.b16 {%0,%1,%2,%3}, [%4];"
                        : "=r"(bf[gj][0]), "=r"(bf[gj][1]), "=r"(bf[gj][2]), "=r"(bf[gj][3])
                        : "r"(addr));
                }
                #pragma unroll
                for (int mi = 0; mi < 2; mi++)
                    #pragma unroll
                    for (int gj = 0; gj < 4; gj++) {
                        #pragma unroll
                        for (int h = 0; h < 2; h++) {
                            int fj = gj * 2 + h;
                            asm volatile(
                                "mma.sync.aligned.m16n8k16.row.col.f32.bf16.bf16.f32 "
                                "{%0,%1,%2,%3},{%4,%5,%6,%7},{%8,%9},{%0,%1,%2,%3};"
                                : "+f"(acc[mi][fj][0]), "+f"(acc[mi][fj][1]),
                                  "+f"(acc[mi][fj][2]), "+f"(acc[mi][fj][3])
                                : "r"(af[mi][0]), "r"(af[mi][1]), "r"(af[mi][2]), "r"(af[mi][3]),
                                  "r"(bf[gj][h * 2]), "r"(bf[gj][h * 2 + 1]));
                        }
                    }
            }
        }
        if (c + 1 < NC) {
            stsA(stage ^ 1);
            asm volatile("cp.async.wait_group 0;");
        }
        __syncthreads();
    }

    // ---- epilogue ----
    float* dst = (DST == 0) ? Cg : g_H;
    int mrow = row0 + warp_m * 32 + (lane >> 2);
    int ncol = n0 + warp_n * 64 + (lane & 3) * 2;
    #pragma unroll
    for (int mi = 0; mi < 2; mi++) {
        int r0 = mrow + mi * 16;
        #pragma unroll
        for (int fj = 0; fj < 8; fj++) {
            int col = ncol + fj * 8;
            float2 bv = *(const float2*)(bias + col);
            float v0 = acc[mi][fj][0] + bv.x;
            float v1 = acc[mi][fj][1] + bv.y;
            float v2 = acc[mi][fj][2] + bv.x;
            float v3 = acc[mi][fj][3] + bv.y;
            if (RELU) {
                v0 = fmaxf(v0, 0.f); v1 = fmaxf(v1, 0.f);
                v2 = fmaxf(v2, 0.f); v3 = fmaxf(v3, 0.f);
            }
            if (r0 < Meff)     *(float2*)(dst + (size_t)r0 * NTOT + col)       = make_float2(v0, v1);
            if (r0 + 8 < Meff) *(float2*)(dst + (size_t)(r0 + 8) * NTOT + col) = make_float2(v2, v3);
        }
    }
}

// ---------------- size-pred epilogue: LN + relu + @sp_W2 + argmax ----------------
__global__ void sizepred_kernel(const float* __restrict__ W2, const float* __restrict__ b2,
                                const float* __restrict__ g1, const float* __restrict__ be1)
{
    int w = (blockIdx.x * blockDim.x + threadIdx.x) >> 5;
    int lane = threadIdx.x & 31;
    if (w >= NB) return;
    const float* u = g_U + (size_t)w * KMID;
    float vals[9];
    float s = 0.f, sq = 0.f;
    #pragma unroll
    for (int i = 0; i < 9; i++) {
        int j = lane + 32 * i;
        float v = (j < KMID) ? u[j] : 0.f;
        vals[i] = v; s += v; sq += v * v;
    }
    for (int d = 16; d; d >>= 1) { s += __shfl_xor_sync(~0u, s, d); sq += __shfl_xor_sync(~0u, sq, d); }
    float mean = s * (1.f / KMID);
    float var  = sq * (1.f / KMID) - mean * mean;
    float inv  = rsqrtf(var + 1e-5f);
    float logit[MAXN];
    #pragma unroll
    for (int o = 0; o < MAXN; o++) logit[o] = 0.f;
    #pragma unroll
    for (int i = 0; i < 9; i++) {
        int j = lane + 32 * i;
        if (j < KMID) {
            float h = fmaxf((vals[i] - mean) * inv * g1[j] + be1[j], 0.f);
            #pragma unroll
            for (int o = 0; o < MAXN; o++) logit[o] += h * W2[j * MAXN + o];
        }
    }
    #pragma unroll
    for (int o = 0; o < MAXN; o++)
        for (int d = 16; d; d >>= 1) logit[o] += __shfl_xor_sync(~0u, logit[o], d);
    if (lane == 0) {
        float best = -1e30f; int bi = 0;
        #pragma unroll
        for (int o = 0; o < MAXN; o++) {
            float v = logit[o] + b2[o];
            if (v > best) { best = v; bi = o; }
        }
        g_n[w] = bi;
    }
}

// ---------------- exclusive scan (shfl-based) ----------------
__global__ void scan_kernel()
{
    __shared__ int warpsum[32];
    int t = threadIdx.x, l = t & 31, w = t >> 5;
    int base = t * 32;
    int loc[32];
    int s = 0;
    #pragma unroll
    for (int i = 0; i < 32; i++) { loc[i] = s; s += g_n[base + i]; }
    int inc = s;
    #pragma unroll
    for (int d = 1; d < 32; d <<= 1) { int v = __shfl_up_sync(~0u, inc, d); if (l >= d) inc += v; }
    if (l == 31) warpsum[w] = inc;
    __syncthreads();
    if (w == 0) {
        int v = warpsum[l];
        #pragma unroll
        for (int d = 1; d < 32; d <<= 1) { int u2 = __shfl_up_sync(~0u, v, d); if (l >= d) v += u2; }
        warpsum[l] = v;
    }
    __syncthreads();
    int wbase = (w > 0) ? warpsum[w - 1] : 0;
    int exc = wbase + inc - s;
    #pragma unroll
    for (int i = 0; i < 32; i++) g_off[base + i] = exc + loc[i];
    if (t == 1023) g_total = wbase + inc;
}

__global__ void tokmap_kernel()
{
    int b = blockIdx.x * 256 + threadIdx.x;
    if (b >= NB) return;
    int off = g_off[b], n = g_n[b];
    for (int j = 0; j < n; j++) { g_tok_b[off + j] = b; g_tok_k[off + j] = (unsigned char)j; }
}

__global__ void batchout_kernel(float* __restrict__ out, long long out_size)
{
    int t = blockIdx.x * 256 + threadIdx.x;
    int total = g_total;
    if ((long long)total * 257 > out_size) return;
    if (t < total) out[(long long)total * 256 + t] = (float)g_tok_b[t];
}

// ---------------- launch ----------------
extern "C" void kernel_launch(void* const* d_in, const int* in_sizes, int n_in,
                              void* d_out, int out_size)
{
    const float* z     = (const float*)d_in[0];
    const float* kW1   = (const float*)d_in[1];
    const float* kb1   = (const float*)d_in[2];
    const float* kg1   = (const float*)d_in[3];
    const float* kbe1  = (const float*)d_in[4];
    const float* kW2   = (const float*)d_in[5];
    const float* kb2   = (const float*)d_in[6];
    const float* dW1   = (const float*)d_in[7];
    const float* db1   = (const float*)d_in[8];
    const float* dW2   = (const float*)d_in[9];
    const float* db2   = (const float*)d_in[10];
    const float* spW1  = (const float*)d_in[11];
    const float* spb1  = (const float*)d_in[12];
    const float* spg1  = (const float*)d_in[13];
    const float* spbe1 = (const float*)d_in[14];
    const float* spW2  = (const float*)d_in[15];
    const float* spb2  = (const float*)d_in[16];
    float* out = (float*)d_out;

    constexpr int SMEM_HMMA = 2 * STG_BYTES;  // 147456
    cudaFuncSetAttribute(hmma_gemm<1, DMID, HID, 1, 2, B1_OFF>,
                         cudaFuncAttributeMaxDynamicSharedMemorySize, SMEM_HMMA);
    cudaFuncSetAttribute(hmma_gemm<2, DIM, DMID, 0, 0, B2_OFF>,
                         cudaFuncAttributeMaxDynamicSharedMemorySize, SMEM_HMMA);

    // weight prep
    prep_kernel<B1_OFF><<<(DMID * (HID / 8) + 255) / 256, 256>>>(dW1, HID, DMID);
    prep_kernel<B2_OFF><<<(DIM * (DMID / 8) + 255) / 256, 256>>>(dW2, DMID, DIM);

    // 17 key rows
    keys_kernel<<<17, 256>>>(kW1, kb1, kg1, kbe1, kW2, kb2);

    // sp GEMM (fp32, argmax-safe): U = z @ spW1 + b
    gemm32_sp<<<dim3((KMID + BN - 1) / BN, NB / BM), 128>>>(z, spW1, spb1);

    // size-pred -> g_n -> offsets -> token map
    sizepred_kernel<<<(NB * 32) / 256, 256>>>(spW2, spb2, spg1, spbe1);
    scan_kernel<<<1, 1024>>>();
    tokmap_kernel<<<NB / 256, 256>>>();

    // dec1: H = relu((z[b]*keys[k]) @ dW1 + b1)  [T x 384]
    hmma_gemm<1, DMID, HID, 1, 2, B1_OFF>
        <<<dim3(TMAX / 128, DMID / 128), 256, SMEM_HMMA>>>(z, db1, nullptr);

    // dec2: out = H @ dW2 + b2  [T x 256]
    hmma_gemm<2, DIM, DMID, 0, 0, B2_OFF>
        <<<dim3(TMAX / 128, DIM / 128), 256, SMEM_HMMA>>>(nullptr, db2, out);

    // optional batch ids
    batchout_kernel<<<TMAX / 256, 256>>>(out, (long long)out_size);
}

// round 7
// speedup vs baseline: 2.2973x; 1.0046x over previous
#include <cuda_runtime.h>
#include <cuda_bf16.h>
#include <cstdint>
#include <cstddef>

// Problem constants
#define NB    32768
#define HID   512
#define KMID  264
#define DMID  384
#define DIM   256
#define MAXN  17
#define TMAX  (NB * 16)   // 524288 worst-case tokens

// ---------------- static device scratch ----------------
__device__ __align__(16) float g_keys[MAXN * HID];
__device__ __align__(16) float g_U[(size_t)NB * KMID];
__device__ int   g_n[NB];
__device__ int   g_off[NB];
__device__ int   g_total;
__device__ int   g_tok_b[TMAX];
__device__ unsigned char g_tok_k[TMAX];

// pre-split bf16 weights (tiny): element (chunk c, col n, klocal) at (c*N + n)*72 + kl
#define B1_ELEMS (8 * DMID * 72)
#define B2_ELEMS (6 * DIM * 72)
#define B1_OFF 0
#define B2_OFF B1_ELEMS
__device__ __align__(16) __nv_bfloat16 g_Bh[B1_ELEMS + B2_ELEMS];
__device__ __align__(16) __nv_bfloat16 g_Bl[B1_ELEMS + B2_ELEMS];

// pre-split A (z[b]*keys[k]) and H, PACKED 128-row tile slabs (64 elems = 128B per row):
// element (rowtile rt, chunk c, row rl, klocal kl) at ((rt*NC + c)*128 + rl)*64 + kl
__device__ __align__(16) __nv_bfloat16 g_Ah[(size_t)TMAX * 8 * 64];   // 512 MiB
__device__ __align__(16) __nv_bfloat16 g_Al[(size_t)TMAX * 8 * 64];   // 512 MiB
__device__ __align__(16) __nv_bfloat16 g_Hh[(size_t)TMAX * 6 * 64];   // 384 MiB
__device__ __align__(16) __nv_bfloat16 g_Hl[(size_t)TMAX * 6 * 64];   // 384 MiB

__device__ __forceinline__ uint32_t smem_u32(const void* p) {
    uint32_t a;
    asm("{ .reg .u64 t; cvta.to.shared.u64 t, %1; cvt.u32.u64 %0, t; }" : "=r"(a) : "l"(p));
    return a;
}

__device__ __forceinline__ void split_pair(float a, float b, uint32_t& hi, uint32_t& lo) {
    __nv_bfloat16 h0 = __float2bfloat16(a), h1 = __float2bfloat16(b);
    float f0 = __bfloat162float(h0), f1 = __bfloat162float(h1);
    __nv_bfloat16 l0 = __float2bfloat16(a - f0), l1 = __float2bfloat16(b - f1);
    hi = (uint32_t)__bfloat16_as_ushort(h0) | ((uint32_t)__bfloat16_as_ushort(h1) << 16);
    lo = (uint32_t)__bfloat16_as_ushort(l0) | ((uint32_t)__bfloat16_as_ushort(l1) << 16);
}

// ---------------- weight prep: W[K,N] fp32 -> hi/lo bf16, [c][n][72] ----------------
template<int BOFF>
__global__ void prep_kernel(const float* __restrict__ W, int K, int N)
{
    int t = blockIdx.x * 256 + threadIdx.x;
    int total = N * (K / 8);
    if (t >= total) return;
    int n  = t / (K / 8);
    int k0 = (t % (K / 8)) * 8;
    uint32_t hi[4], lo[4];
    #pragma unroll
    for (int q = 0; q < 4; q++) {
        float va = W[(size_t)(k0 + 2 * q) * N + n];
        float vb = W[(size_t)(k0 + 2 * q + 1) * N + n];
        split_pair(va, vb, hi[q], lo[q]);
    }
    int c  = k0 / 64;
    int kl = k0 % 64;
    size_t off = ((size_t)BOFF + ((size_t)c * N + n) * 72 + kl) * 2;
    *(uint4*)((char*)g_Bh + off) = make_uint4(hi[0], hi[1], hi[2], hi[3]);
    *(uint4*)((char*)g_Bl + off) = make_uint4(lo[0], lo[1], lo[2], lo[3]);
}

// ---------------- keys precompute (17 rows x 8 col-chunks) ----------------
__global__ void keys_kernel(const float* __restrict__ kW1, const float* __restrict__ kb1,
                            const float* __restrict__ kg1, const float* __restrict__ kbe1,
                            const float* __restrict__ kW2, const float* __restrict__ kb2)
{
    int k = blockIdx.x;
    __shared__ float h[KMID];
    __shared__ float red[18];
    int t = threadIdx.x;   // 256
    float s = 0.f, sq = 0.f;
    for (int j = t; j < KMID; j += 256) {
        float u = kW1[k * KMID + j] + kb1[j];
        h[j] = u; s += u; sq += u * u;
    }
    for (int d = 16; d; d >>= 1) { s += __shfl_xor_sync(~0u, s, d); sq += __shfl_xor_sync(~0u, sq, d); }
    if ((t & 31) == 0) { red[t >> 5] = s; red[8 + (t >> 5)] = sq; }
    __syncthreads();
    if (t == 0) {
        float S = 0.f, SQ = 0.f;
        for (int i = 0; i < 8; i++) { S += red[i]; SQ += red[8 + i]; }
        red[16] = S; red[17] = SQ;
    }
    __syncthreads();
    float mean = red[16] * (1.f / KMID);
    float var  = red[17] * (1.f / KMID) - mean * mean;
    float inv  = rsqrtf(var + 1e-5f);
    for (int j = t; j < KMID; j += 256)
        h[j] = fmaxf((h[j] - mean) * inv * kg1[j] + kbe1[j], 0.f);
    __syncthreads();
    if (t < 64) {
        int c = blockIdx.y * 64 + t;
        float acc = kb2[c];
        #pragma unroll 4
        for (int j = 0; j < KMID; j++) acc += h[j] * kW2[(size_t)j * HID + c];
        g_keys[k * HID + c] = acc;
    }
}

// ---------------- fp32 SIMT GEMM for size-pred path (bit-exact argmax safety) ----------------
#define BM 128
#define BN 64
#define BK 16
__global__ void __launch_bounds__(128)
gemm32_sp(const float* __restrict__ Ag, const float* __restrict__ Wg,
          const float* __restrict__ bias)
{
    const int N = KMID, K = HID;
    int row0 = blockIdx.y * BM;
    int col0 = blockIdx.x * BN;

    __shared__ float As[BK][BM];
    __shared__ float Bs[BK][BN];

    int tid = threadIdx.x;
    const float* arow = Ag + (size_t)(row0 + tid) * K;

    float acc[8][8];
    #pragma unroll
    for (int i = 0; i < 8; i++)
        #pragma unroll
        for (int j = 0; j < 8; j++) acc[i][j] = 0.f;

    int tr  = tid & 15;
    int tcg = tid >> 4;

    for (int k0 = 0; k0 < K; k0 += BK) {
        #pragma unroll
        for (int i = 0; i < BK; i += 4) {
            float4 v = *(const float4*)(arow + k0 + i);
            As[i + 0][tid] = v.x; As[i + 1][tid] = v.y;
            As[i + 2][tid] = v.z; As[i + 3][tid] = v.w;
        }
        #pragma unroll
        for (int i = 0; i < 8; i++) {
            int e  = tid + 128 * i;
            int br = e >> 6;
            int bc = e & 63;
            int col = col0 + bc;
            Bs[br][bc] = (col < N) ? Wg[(size_t)(k0 + br) * N + col] : 0.f;
        }
        __syncthreads();
        #pragma unroll
        for (int k = 0; k < BK; k++) {
            float a[8], b[8];
            #pragma unroll
            for (int i = 0; i < 8; i++) a[i] = As[k][tr * 8 + i];
            #pragma unroll
            for (int j = 0; j < 8; j++) b[j] = Bs[k][tcg * 8 + j];
            #pragma unroll
            for (int i = 0; i < 8; i++)
                #pragma unroll
                for (int j = 0; j < 8; j++)
                    acc[i][j] = fmaf(a[i], b[j], acc[i][j]);
        }
        __syncthreads();
    }
    #pragma unroll
    for (int i = 0; i < 8; i++) {
        int row = row0 + tr * 8 + i;
        #pragma unroll
        for (int j = 0; j < 8; j++) {
            int col = col0 + tcg * 8 + j;
            if (col < N) g_U[(size_t)row * N + col] = acc[i][j] + bias[col];
        }
    }
}

// ---------------- size-pred: LN + relu + @sp_W2 + argmax ----------------
__global__ void __launch_bounds__(256)
sizepred_kernel(const float* __restrict__ W2, const float* __restrict__ b2,
                const float* __restrict__ g1, const float* __restrict__ be1)
{
    __shared__ float sW2[KMID * MAXN];
    int tid = threadIdx.x;
    for (int i = tid; i < KMID * MAXN; i += 256) sW2[i] = W2[i];
    __syncthreads();

    int w = blockIdx.x * 8 + (tid >> 5);
    int lane = tid & 31;
    if (w >= NB) return;
    const float* u = g_U + (size_t)w * KMID;
    float vals[9];
    float s = 0.f, sq = 0.f;
    #pragma unroll
    for (int i = 0; i < 9; i++) {
        int j = lane + 32 * i;
        float v = (j < KMID) ? u[j] : 0.f;
        vals[i] = v; s += v; sq += v * v;
    }
    for (int d = 16; d; d >>= 1) { s += __shfl_xor_sync(~0u, s, d); sq += __shfl_xor_sync(~0u, sq, d); }
    float mean = s * (1.f / KMID);
    float var  = sq * (1.f / KMID) - mean * mean;
    float inv  = rsqrtf(var + 1e-5f);
    float logit[MAXN];
    #pragma unroll
    for (int o = 0; o < MAXN; o++) logit[o] = 0.f;
    #pragma unroll
    for (int i = 0; i < 9; i++) {
        int j = lane + 32 * i;
        if (j < KMID) {
            float h = fmaxf((vals[i] - mean) * inv * g1[j] + be1[j], 0.f);
            #pragma unroll
            for (int o = 0; o < MAXN; o++) logit[o] += h * sW2[j * MAXN + o];
        }
    }
    #pragma unroll
    for (int o = 0; o < MAXN; o++)
        for (int d = 16; d; d >>= 1) logit[o] += __shfl_xor_sync(~0u, logit[o], d);
    if (lane == 0) {
        float best = -1e30f; int bi = 0;
        #pragma unroll
        for (int o = 0; o < MAXN; o++) {
            float v = logit[o] + b2[o];
            if (v > best) { best = v; bi = o; }
        }
        g_n[w] = bi;
    }
}

// ---------------- exclusive scan ----------------
__global__ void scan_kernel()
{
    __shared__ int warpsum[32];
    int t = threadIdx.x, l = t & 31, w = t >> 5;
    int base = t * 32;
    int loc[32];
    int s = 0;
    #pragma unroll
    for (int i = 0; i < 32; i++) { loc[i] = s; s += g_n[base + i]; }
    int inc = s;
    #pragma unroll
    for (int d = 1; d < 32; d <<= 1) { int v = __shfl_up_sync(~0u, inc, d); if (l >= d) inc += v; }
    if (l == 31) warpsum[w] = inc;
    __syncthreads();
    if (w == 0) {
        int v = warpsum[l];
        #pragma unroll
        for (int d = 1; d < 32; d <<= 1) { int u2 = __shfl_up_sync(~0u, v, d); if (l >= d) v += u2; }
        warpsum[l] = v;
    }
    __syncthreads();
    int wbase = (w > 0) ? warpsum[w - 1] : 0;
    int exc = wbase + inc - s;
    #pragma unroll
    for (int i = 0; i < 32; i++) g_off[base + i] = exc + loc[i];
    if (t == 1023) g_total = wbase + inc;
}

__global__ void tokmap_kernel()
{
    int b = blockIdx.x * 256 + threadIdx.x;
    if (b >= NB) return;
    int off = g_off[b], n = g_n[b];
    for (int j = 0; j < n; j++) { g_tok_b[off + j] = b; g_tok_k[off + j] = (unsigned char)j; }
}

// ---------------- gatherA: zp = z[b]*keys[k], split hi/lo, PACKED 128-row slabs ----------------
__global__ void gatherA_kernel(const float* __restrict__ z)
{
    int idx = blockIdx.x * 256 + threadIdx.x;
    int T = g_total;
    int rp = (T + 127) & ~127;          // padded rows (tiles fully covered)
    if (idx >= rp * 4) return;
    int row = idx >> 2, q = idx & 3;
    int rc = min(row, T - 1);
    int b  = g_tok_b[rc];
    int kk = g_tok_k[rc];
    const float* zr = z + (size_t)b * HID;
    const float* kr = g_keys + kk * HID;
    int rt = row >> 7, rl = row & 127;
    #pragma unroll
    for (int jj = 0; jj < 16; jj++) {
        int kg = q * 128 + jj * 8;
        float4 a0 = *(const float4*)(zr + kg),     a1 = *(const float4*)(zr + kg + 4);
        float4 k0 = *(const float4*)(kr + kg),     k1 = *(const float4*)(kr + kg + 4);
        float f[8] = { a0.x * k0.x, a0.y * k0.y, a0.z * k0.z, a0.w * k0.w,
                       a1.x * k1.x, a1.y * k1.y, a1.z * k1.z, a1.w * k1.w };
        uint32_t hi[4], lo[4];
        #pragma unroll
        for (int p = 0; p < 4; p++) split_pair(f[2 * p], f[2 * p + 1], hi[p], lo[p]);
        int c = kg >> 6, kl = kg & 63;
        size_t off = (((size_t)(rt * 8 + c) * 128 + rl) * 64 + kl) * 2;   // packed: 64 elems/row
        *(uint4*)((char*)g_Ah + off) = make_uint4(hi[0], hi[1], hi[2], hi[3]);
        *(uint4*)((char*)g_Al + off) = make_uint4(lo[0], lo[1], lo[2], lo[3]);
    }
}

// ---------------- split-bf16 HMMA GEMM, pure-copy operands ----------------
// ALL scratch arrays referenced DEVICE-SIDE via template params (never as host-passed
// symbol args — host-side decay of __device__ symbols gives the host shadow address,
// which GB300's ATS silently reads as zeros; that was the rounds-4/5/6 bug).
// ASEL 0: A = g_Ah/g_Al slabs; ASEL 1: A = g_Hh/g_Hl slabs. BOFF: offset into g_Bh/g_Bl.
// CTA tile 128x128, 8 warps (warp tile 32x64), proven geometry & 147456B smem.
template<int ASEL, int NTOT, int KTOT, int EMODE, int RELU, int BOFF>
__global__ void __launch_bounds__(256, 1)
hmma2(const float* __restrict__ bias, float* __restrict__ Cg)
{
    constexpr int NC  = KTOT / 64;
    constexpr int CB  = 128 * 144;               // smem bytes per component per chunk
    constexpr int CBG = 128 * 128;               // gmem bytes per A-slab chunk (packed)
    constexpr int AHo = 0, ALo = CB, BHo = 2 * CB, BLo = 3 * CB;
    constexpr int STG = 4 * CB;                  // 73728; x2 stages = 147456

    int Meff = g_total;
    int row0 = blockIdx.x * 128;
    if (row0 >= Meff) return;
    int n0 = blockIdx.y * 128;

    // device-side symbol references (the fix)
    const char* Ahg = (const char*)(ASEL == 0 ? g_Ah : g_Hh);
    const char* Alg = (const char*)(ASEL == 0 ? g_Al : g_Hl);
    const char* Bhg = (const char*)g_Bh + (size_t)BOFF * 2;
    const char* Blg = (const char*)g_Bl + (size_t)BOFF * 2;

    extern __shared__ char dyn[];
    const uint32_t dynb = smem_u32(dyn);
    int tid  = threadIdx.x;
    int wid  = tid >> 5;
    int lane = tid & 31;
    int warp_m = wid & 3;     // 4 x 32 rows
    int warp_n = wid >> 2;    // 2 x 64 cols

    auto cpA = [&](int c, int st) {
        uint32_t dh = dynb + st * STG + AHo;
        uint32_t dl = dynb + st * STG + ALo;
        const char* sh = Ahg + (size_t)(blockIdx.x * NC + c) * CBG;
        const char* sl = Alg + (size_t)(blockIdx.x * NC + c) * CBG;
        #pragma unroll
        for (int it = 0; it < 4; it++) {
            int tt = tid + 256 * it;       // 1024 tasks exactly (128 rows x 8 segs)
            int row = tt >> 3, sg = tt & 7;
            uint32_t so  = row * 128 + sg * 16;
            uint32_t dof = row * 144 + sg * 16;
            asm volatile("cp.async.cg.shared.global [%0], [%1], 16;" :: "r"(dh + dof), "l"(sh + so));
            asm volatile("cp.async.cg.shared.global [%0], [%1], 16;" :: "r"(dl + dof), "l"(sl + so));
        }
    };
    auto cpB = [&](int c, int st) {
        uint32_t dh = dynb + st * STG + BHo;
        uint32_t dl = dynb + st * STG + BLo;
        const char* sh = Bhg + ((size_t)c * NTOT + n0) * 144;
        const char* sl = Blg + ((size_t)c * NTOT + n0) * 144;
        #pragma unroll
        for (int it = 0; it < 5; it++) {
            int tt = tid + 256 * it;
            if (tt < 128 * 9) {
                int row = tt / 9, sg = tt - row * 9;
                uint32_t o = row * 144 + sg * 16;
                asm volatile("cp.async.cg.shared.global [%0], [%1], 16;" :: "r"(dh + o), "l"(sh + o));
                asm volatile("cp.async.cg.shared.global [%0], [%1], 16;" :: "r"(dl + o), "l"(sl + o));
            }
        }
    };

    float acc[2][8][4];
    #pragma unroll
    for (int mi = 0; mi < 2; mi++)
        #pragma unroll
        for (int fj = 0; fj < 8; fj++)
            #pragma unroll
            for (int q = 0; q < 4; q++) acc[mi][fj][q] = 0.f;

    uint32_t a_off = (uint32_t)(warp_m * 32 + (lane & 15)) * 144 + ((lane >> 4) << 3) * 2;
    uint32_t b_off = (uint32_t)(warp_n * 64 + (lane & 7) + ((lane >> 4) << 3)) * 144
                   + (((lane >> 3) & 1) << 3) * 2;

    cpA(0, 0); cpB(0, 0);
    asm volatile("cp.async.commit_group;");
    asm volatile("cp.async.wait_group 0;");
    __syncthreads();

    for (int c = 0; c < NC; c++) {
        int st = c & 1;
        if (c + 1 < NC) {
            cpA(c + 1, st ^ 1); cpB(c + 1, st ^ 1);
            asm volatile("cp.async.commit_group;");
        }
        uint32_t sb = dynb + st * STG;
        #pragma unroll
        for (int p = 0; p < 3; p++) {
            uint32_t Ab = sb + (p == 2 ? ALo : AHo) + a_off;
            uint32_t Bb = sb + (p == 1 ? BLo : BHo) + b_off;
            #pragma unroll
            for (int k16 = 0; k16 < 4; k16++) {
                uint32_t kb = (uint32_t)k16 * 32;
                uint32_t af[2][4];
                #pragma unroll
                for (int mi = 0; mi < 2; mi++) {
                    uint32_t addr = Ab + mi * 2304 + kb;   // 16 rows * 144B
                    asm volatile("ldmatrix.sync.aligned.m8n8.x4.shared.b16 {%0,%1,%2,%3}, [%4];"
                        : "=r"(af[mi][0]), "=r"(af[mi][1]), "=r"(af[mi][2]), "=r"(af[mi][3])
                        : "r"(addr));
                }
                uint32_t bf[4][4];
                #pragma unroll
                for (int gj = 0; gj < 4; gj++) {
                    uint32_t addr = Bb + gj * 2304 + kb;
                    asm volatile("ldmatrix.sync.aligned.m8n8.x4.shared.b16 {%0,%1,%2,%3}, [%4];"
                        : "=r"(bf[gj][0]), "=r"(bf[gj][1]), "=r"(bf[gj][2]), "=r"(bf[gj][3])
                        : "r"(addr));
                }
                #pragma unroll
                for (int mi = 0; mi < 2; mi++)
                    #pragma unroll
                    for (int gj = 0; gj < 4; gj++) {
                        #pragma unroll
                        for (int h = 0; h < 2; h++) {
                            int fj = gj * 2 + h;
                            asm volatile(
                                "mma.sync.aligned.m16n8k16.row.col.f32.bf16.bf16.f32 "
                                "{%0,%1,%2,%3},{%4,%5,%6,%7},{%8,%9},{%0,%1,%2,%3};"
                                : "+f"(acc[mi][fj][0]), "+f"(acc[mi][fj][1]),
                                  "+f"(acc[mi][fj][2]), "+f"(acc[mi][fj][3])
                                : "r"(af[mi][0]), "r"(af[mi][1]), "r"(af[mi][2]), "r"(af[mi][3]),
                                  "r"(bf[gj][h * 2]), "r"(bf[gj][h * 2 + 1]));
                        }
                    }
            }
        }
        asm volatile("cp.async.wait_group 0;");
        __syncthreads();
    }

    // ---- epilogue ----
    int rl_base = warp_m * 32 + (lane >> 2);
    int cl_base = warp_n * 64 + (lane & 3) * 2;
    if (EMODE == 0) {
        #pragma unroll
        for (int mi = 0; mi < 2; mi++) {
            int r0 = row0 + rl_base + mi * 16;
            #pragma unroll
            for (int fj = 0; fj < 8; fj++) {
                int col = n0 + cl_base + fj * 8;
                float2 bv = *(const float2*)(bias + col);
                float v0 = acc[mi][fj][0] + bv.x;
                float v1 = acc[mi][fj][1] + bv.y;
                float v2 = acc[mi][fj][2] + bv.x;
                float v3 = acc[mi][fj][3] + bv.y;
                if (RELU) { v0 = fmaxf(v0, 0.f); v1 = fmaxf(v1, 0.f); v2 = fmaxf(v2, 0.f); v3 = fmaxf(v3, 0.f); }
                if (r0 < Meff)     *(float2*)(Cg + (size_t)r0 * NTOT + col)       = make_float2(v0, v1);
                if (r0 + 8 < Meff) *(float2*)(Cg + (size_t)(r0 + 8) * NTOT + col) = make_float2(v2, v3);
            }
        }
    } else {
        // split-bf16 H out, PACKED 128-row slabs: ((rt*6 + hc)*128 + row)*64 + kl
        #pragma unroll
        for (int mi = 0; mi < 2; mi++) {
            #pragma unroll
            for (int fj = 0; fj < 8; fj++) {
                int colg = n0 + cl_base + fj * 8;
                int hc = colg >> 6, kl = colg & 63;
                float2 bv = *(const float2*)(bias + colg);
                #pragma unroll
                for (int h2 = 0; h2 < 2; h2++) {
                    int row_l = rl_base + mi * 16 + h2 * 8;
                    float v0 = acc[mi][fj][h2 * 2 + 0] + bv.x;
                    float v1 = acc[mi][fj][h2 * 2 + 1] + bv.y;
                    if (RELU) { v0 = fmaxf(v0, 0.f); v1 = fmaxf(v1, 0.f); }
                    uint32_t hi, lo;
                    split_pair(v0, v1, hi, lo);
                    size_t off = (((size_t)(blockIdx.x * 6 + hc) * 128 + row_l) * 64 + kl) * 2;
                    *(uint32_t*)((char*)g_Hh + off) = hi;
                    *(uint32_t*)((char*)g_Hl + off) = lo;
                }
            }
        }
    }
}

__global__ void batchout_kernel(float* __restrict__ out, long long out_size)
{
    int t = blockIdx.x * 256 + threadIdx.x;
    int total = g_total;
    if ((long long)total * 257 > out_size) return;
    if (t < total) out[(long long)total * 256 + t] = (float)g_tok_b[t];
}

// ---------------- launch ----------------
extern "C" void kernel_launch(void* const* d_in, const int* in_sizes, int n_in,
                              void* d_out, int out_size)
{
    const float* z     = (const float*)d_in[0];
    const float* kW1   = (const float*)d_in[1];
    const float* kb1   = (const float*)d_in[2];
    const float* kg1   = (const float*)d_in[3];
    const float* kbe1  = (const float*)d_in[4];
    const float* kW2   = (const float*)d_in[5];
    const float* kb2   = (const float*)d_in[6];
    const float* dW1   = (const float*)d_in[7];
    const float* db1   = (const float*)d_in[8];
    const float* dW2   = (const float*)d_in[9];
    const float* db2   = (const float*)d_in[10];
    const float* spW1  = (const float*)d_in[11];
    const float* spb1  = (const float*)d_in[12];
    const float* spg1  = (const float*)d_in[13];
    const float* spbe1 = (const float*)d_in[14];
    const float* spW2  = (const float*)d_in[15];
    const float* spb2  = (const float*)d_in[16];
    float* out = (float*)d_out;

    constexpr int SMEM_HMMA = 2 * 4 * 128 * 144;   // 147456 (proven size)
    cudaFuncSetAttribute(hmma2<0, DMID, HID, 1, 1, B1_OFF>,
                         cudaFuncAttributeMaxDynamicSharedMemorySize, SMEM_HMMA);
    cudaFuncSetAttribute(hmma2<1, DIM, DMID, 0, 0, B2_OFF>,
                         cudaFuncAttributeMaxDynamicSharedMemorySize, SMEM_HMMA);

    // weight prep
    prep_kernel<B1_OFF><<<(DMID * (HID / 8) + 255) / 256, 256>>>(dW1, HID, DMID);
    prep_kernel<B2_OFF><<<(DIM * (DMID / 8) + 255) / 256, 256>>>(dW2, DMID, DIM);

    // 17 key rows
    keys_kernel<<<dim3(17, 8), 256>>>(kW1, kb1, kg1, kbe1, kW2, kb2);

    // sp GEMM (fp32, bit-exact argmax path)
    gemm32_sp<<<dim3((KMID + BN - 1) / BN, NB / BM), 128>>>(z, spW1, spb1);

    // size-pred -> g_n -> offsets -> token map
    sizepred_kernel<<<NB / 8, 256>>>(spW2, spb2, spg1, spbe1);
    scan_kernel<<<1, 1024>>>();
    tokmap_kernel<<<NB / 256, 256>>>();

    // pre-split A = z[b]*keys[k]
    gatherA_kernel<<<TMAX * 4 / 256, 256>>>(z);

    // dec1: H = relu(A @ dW1 + b1) -> split-bf16 H slabs   [T x 384]
    hmma2<0, DMID, HID, 1, 1, B1_OFF>
        <<<dim3(TMAX / 128, DMID / 128), 256, SMEM_HMMA>>>(db1, nullptr);

    // dec2: out = H @ dW2 + b2   [T x 256]
    hmma2<1, DIM, DMID, 0, 0, B2_OFF>
        <<<dim3(TMAX / 128, DIM / 128), 256, SMEM_HMMA>>>(db2, out);

    // optional batch ids
    batchout_kernel<<<TMAX / 256, 256>>>(out, (long long)out_size);
}

// round 8
// speedup vs baseline: 2.3076x; 1.0045x over previous
#include <cuda_runtime.h>
#include <cuda_bf16.h>
#include <cstdint>
#include <cstddef>

// Problem constants
#define NB    32768
#define HID   512
#define KMID  264
#define DMID  384
#define DIM   256
#define MAXN  17
#define TMAX  (NB * 16)   // 524288 worst-case tokens

// ---------------- static device scratch ----------------
__device__ __align__(16) float g_keys[MAXN * HID];
__device__ __align__(16) float g_U[(size_t)NB * KMID];
__device__ int   g_n[NB];
__device__ int   g_off[NB];
__device__ int   g_total;
__device__ int   g_tok_b[TMAX];
__device__ unsigned char g_tok_k[TMAX];

// pre-split bf16 weights (tiny): element (chunk c, col n, klocal) at (c*N + n)*72 + kl
#define B1_ELEMS (8 * DMID * 72)
#define B2_ELEMS (6 * DIM * 72)
#define B1_OFF 0
#define B2_OFF B1_ELEMS
__device__ __align__(16) __nv_bfloat16 g_Bh[B1_ELEMS + B2_ELEMS];
__device__ __align__(16) __nv_bfloat16 g_Bl[B1_ELEMS + B2_ELEMS];

// pre-split A (z[b]*keys[k]) and H, PACKED 128-row tile slabs (64 elems = 128B per row):
// element (rowtile rt, chunk c, row rl, klocal kl) at ((rt*NC + c)*128 + rl)*64 + kl
__device__ __align__(16) __nv_bfloat16 g_Ah[(size_t)TMAX * 8 * 64];   // 512 MiB
__device__ __align__(16) __nv_bfloat16 g_Al[(size_t)TMAX * 8 * 64];   // 512 MiB
__device__ __align__(16) __nv_bfloat16 g_Hh[(size_t)TMAX * 6 * 64];   // 384 MiB
__device__ __align__(16) __nv_bfloat16 g_Hl[(size_t)TMAX * 6 * 64];   // 384 MiB

__device__ __forceinline__ uint32_t smem_u32(const void* p) {
    uint32_t a;
    asm("{ .reg .u64 t; cvta.to.shared.u64 t, %1; cvt.u32.u64 %0, t; }" : "=r"(a) : "l"(p));
    return a;
}

__device__ __forceinline__ void split_pair(float a, float b, uint32_t& hi, uint32_t& lo) {
    __nv_bfloat16 h0 = __float2bfloat16(a), h1 = __float2bfloat16(b);
    float f0 = __bfloat162float(h0), f1 = __bfloat162float(h1);
    __nv_bfloat16 l0 = __float2bfloat16(a - f0), l1 = __float2bfloat16(b - f1);
    hi = (uint32_t)__bfloat16_as_ushort(h0) | ((uint32_t)__bfloat16_as_ushort(h1) << 16);
    lo = (uint32_t)__bfloat16_as_ushort(l0) | ((uint32_t)__bfloat16_as_ushort(l1) << 16);
}

// ---------------- weight prep: W[K,N] fp32 -> hi/lo bf16, [c][n][72] ----------------
template<int BOFF>
__global__ void prep_kernel(const float* __restrict__ W, int K, int N)
{
    int t = blockIdx.x * 256 + threadIdx.x;
    int total = N * (K / 8);
    if (t >= total) return;
    int n  = t / (K / 8);
    int k0 = (t % (K / 8)) * 8;
    uint32_t hi[4], lo[4];
    #pragma unroll
    for (int q = 0; q < 4; q++) {
        float va = W[(size_t)(k0 + 2 * q) * N + n];
        float vb = W[(size_t)(k0 + 2 * q + 1) * N + n];
        split_pair(va, vb, hi[q], lo[q]);
    }
    int c  = k0 / 64;
    int kl = k0 % 64;
    size_t off = ((size_t)BOFF + ((size_t)c * N + n) * 72 + kl) * 2;
    *(uint4*)((char*)g_Bh + off) = make_uint4(hi[0], hi[1], hi[2], hi[3]);
    *(uint4*)((char*)g_Bl + off) = make_uint4(lo[0], lo[1], lo[2], lo[3]);
}

// ---------------- keys precompute (17 rows x 8 col-chunks) ----------------
__global__ void keys_kernel(const float* __restrict__ kW1, const float* __restrict__ kb1,
                            const float* __restrict__ kg1, const float* __restrict__ kbe1,
                            const float* __restrict__ kW2, const float* __restrict__ kb2)
{
    int k = blockIdx.x;
    __shared__ float h[KMID];
    __shared__ float red[18];
    int t = threadIdx.x;   // 256
    float s = 0.f, sq = 0.f;
    for (int j = t; j < KMID; j += 256) {
        float u = kW1[k * KMID + j] + kb1[j];
        h[j] = u; s += u; sq += u * u;
    }
    for (int d = 16; d; d >>= 1) { s += __shfl_xor_sync(~0u, s, d); sq += __shfl_xor_sync(~0u, sq, d); }
    if ((t & 31) == 0) { red[t >> 5] = s; red[8 + (t >> 5)] = sq; }
    __syncthreads();
    if (t == 0) {
        float S = 0.f, SQ = 0.f;
        for (int i = 0; i < 8; i++) { S += red[i]; SQ += red[8 + i]; }
        red[16] = S; red[17] = SQ;
    }
    __syncthreads();
    float mean = red[16] * (1.f / KMID);
    float var  = red[17] * (1.f / KMID) - mean * mean;
    float inv  = rsqrtf(var + 1e-5f);
    for (int j = t; j < KMID; j += 256)
        h[j] = fmaxf((h[j] - mean) * inv * kg1[j] + kbe1[j], 0.f);
    __syncthreads();
    if (t < 64) {
        int c = blockIdx.y * 64 + t;
        float acc = kb2[c];
        #pragma unroll 4
        for (int j = 0; j < KMID; j++) acc += h[j] * kW2[(size_t)j * HID + c];
        g_keys[k * HID + c] = acc;
    }
}

// ---------------- fp32 SIMT GEMM for size-pred path (FROZEN: bit-exact argmax safety) ----------------
#define BM 128
#define BN 64
#define BK 16
__global__ void __launch_bounds__(128)
gemm32_sp(const float* __restrict__ Ag, const float* __restrict__ Wg,
          const float* __restrict__ bias)
{
    const int N = KMID, K = HID;
    int row0 = blockIdx.y * BM;
    int col0 = blockIdx.x * BN;

    __shared__ float As[BK][BM];
    __shared__ float Bs[BK][BN];

    int tid = threadIdx.x;
    const float* arow = Ag + (size_t)(row0 + tid) * K;

    float acc[8][8];
    #pragma unroll
    for (int i = 0; i < 8; i++)
        #pragma unroll
        for (int j = 0; j < 8; j++) acc[i][j] = 0.f;

    int tr  = tid & 15;
    int tcg = tid >> 4;

    for (int k0 = 0; k0 < K; k0 += BK) {
        #pragma unroll
        for (int i = 0; i < BK; i += 4) {
            float4 v = *(const float4*)(arow + k0 + i);
            As[i + 0][tid] = v.x; As[i + 1][tid] = v.y;
            As[i + 2][tid] = v.z; As[i + 3][tid] = v.w;
        }
        #pragma unroll
        for (int i = 0; i < 8; i++) {
            int e  = tid + 128 * i;
            int br = e >> 6;
            int bc = e & 63;
            int col = col0 + bc;
            Bs[br][bc] = (col < N) ? Wg[(size_t)(k0 + br) * N + col] : 0.f;
        }
        __syncthreads();
        #pragma unroll
        for (int k = 0; k < BK; k++) {
            float a[8], b[8];
            #pragma unroll
            for (int i = 0; i < 8; i++) a[i] = As[k][tr * 8 + i];
            #pragma unroll
            for (int j = 0; j < 8; j++) b[j] = Bs[k][tcg * 8 + j];
            #pragma unroll
            for (int i = 0; i < 8; i++)
                #pragma unroll
                for (int j = 0; j < 8; j++)
                    acc[i][j] = fmaf(a[i], b[j], acc[i][j]);
        }
        __syncthreads();
    }
    #pragma unroll
    for (int i = 0; i < 8; i++) {
        int row = row0 + tr * 8 + i;
        #pragma unroll
        for (int j = 0; j < 8; j++) {
            int col = col0 + tcg * 8 + j;
            if (col < N) g_U[(size_t)row * N + col] = acc[i][j] + bias[col];
        }
    }
}

// ---------------- size-pred: LN + relu + @sp_W2 + argmax ----------------
__global__ void __launch_bounds__(256)
sizepred_kernel(const float* __restrict__ W2, const float* __restrict__ b2,
                const float* __restrict__ g1, const float* __restrict__ be1)
{
    __shared__ float sW2[KMID * MAXN];
    int tid = threadIdx.x;
    for (int i = tid; i < KMID * MAXN; i += 256) sW2[i] = W2[i];
    __syncthreads();

    int w = blockIdx.x * 8 + (tid >> 5);
    int lane = tid & 31;
    if (w >= NB) return;
    const float* u = g_U + (size_t)w * KMID;
    float vals[9];
    float s = 0.f, sq = 0.f;
    #pragma unroll
    for (int i = 0; i < 9; i++) {
        int j = lane + 32 * i;
        float v = (j < KMID) ? u[j] : 0.f;
        vals[i] = v; s += v; sq += v * v;
    }
    for (int d = 16; d; d >>= 1) { s += __shfl_xor_sync(~0u, s, d); sq += __shfl_xor_sync(~0u, sq, d); }
    float mean = s * (1.f / KMID);
    float var  = sq * (1.f / KMID) - mean * mean;
    float inv  = rsqrtf(var + 1e-5f);
    float logit[MAXN];
    #pragma unroll
    for (int o = 0; o < MAXN; o++) logit[o] = 0.f;
    #pragma unroll
    for (int i = 0; i < 9; i++) {
        int j = lane + 32 * i;
        if (j < KMID) {
            float h = fmaxf((vals[i] - mean) * inv * g1[j] + be1[j], 0.f);
            #pragma unroll
            for (int o = 0; o < MAXN; o++) logit[o] += h * sW2[j * MAXN + o];
        }
    }
    #pragma unroll
    for (int o = 0; o < MAXN; o++)
        for (int d = 16; d; d >>= 1) logit[o] += __shfl_xor_sync(~0u, logit[o], d);
    if (lane == 0) {
        float best = -1e30f; int bi = 0;
        #pragma unroll
        for (int o = 0; o < MAXN; o++) {
            float v = logit[o] + b2[o];
            if (v > best) { best = v; bi = o; }
        }
        g_n[w] = bi;
    }
}

// ---------------- exclusive scan ----------------
__global__ void scan_kernel()
{
    __shared__ int warpsum[32];
    int t = threadIdx.x, l = t & 31, w = t >> 5;
    int base = t * 32;
    int loc[32];
    int s = 0;
    #pragma unroll
    for (int i = 0; i < 32; i++) { loc[i] = s; s += g_n[base + i]; }
    int inc = s;
    #pragma unroll
    for (int d = 1; d < 32; d <<= 1) { int v = __shfl_up_sync(~0u, inc, d); if (l >= d) inc += v; }
    if (l == 31) warpsum[w] = inc;
    __syncthreads();
    if (w == 0) {
        int v = warpsum[l];
        #pragma unroll
        for (int d = 1; d < 32; d <<= 1) { int u2 = __shfl_up_sync(~0u, v, d); if (l >= d) v += u2; }
        warpsum[l] = v;
    }
    __syncthreads();
    int wbase = (w > 0) ? warpsum[w - 1] : 0;
    int exc = wbase + inc - s;
    #pragma unroll
    for (int i = 0; i < 32; i++) g_off[base + i] = exc + loc[i];
    if (t == 1023) g_total = wbase + inc;
}

__global__ void tokmap_kernel()
{
    int b = blockIdx.x * 256 + threadIdx.x;
    if (b >= NB) return;
    int off = g_off[b], n = g_n[b];
    for (int j = 0; j < n; j++) { g_tok_b[off + j] = b; g_tok_k[off + j] = (unsigned char)j; }
}

// ---------------- gatherA: zp = z[b]*keys[k], split hi/lo, PACKED 128-row slabs ----------------
__global__ void gatherA_kernel(const float* __restrict__ z)
{
    int idx = blockIdx.x * 256 + threadIdx.x;
    int T = g_total;
    int rp = (T + 127) & ~127;          // padded rows (tiles fully covered)
    if (idx >= rp * 4) return;
    int row = idx >> 2, q = idx & 3;
    int rc = min(row, T - 1);
    int b  = g_tok_b[rc];
    int kk = g_tok_k[rc];
    const float* zr = z + (size_t)b * HID;
    const float* kr = g_keys + kk * HID;
    int rt = row >> 7, rl = row & 127;
    #pragma unroll
    for (int jj = 0; jj < 16; jj++) {
        int kg = q * 128 + jj * 8;
        float4 a0 = *(const float4*)(zr + kg),     a1 = *(const float4*)(zr + kg + 4);
        float4 k0 = *(const float4*)(kr + kg),     k1 = *(const float4*)(kr + kg + 4);
        float f[8] = { a0.x * k0.x, a0.y * k0.y, a0.z * k0.z, a0.w * k0.w,
                       a1.x * k1.x, a1.y * k1.y, a1.z * k1.z, a1.w * k1.w };
        uint32_t hi[4], lo[4];
        #pragma unroll
        for (int p = 0; p < 4; p++) split_pair(f[2 * p], f[2 * p + 1], hi[p], lo[p]);
        int c = kg >> 6, kl = kg & 63;
        size_t off = (((size_t)(rt * 8 + c) * 128 + rl) * 64 + kl) * 2;   // packed: 64 elems/row
        *(uint4*)((char*)g_Ah + off) = make_uint4(hi[0], hi[1], hi[2], hi[3]);
        *(uint4*)((char*)g_Al + off) = make_uint4(lo[0], lo[1], lo[2], lo[3]);
    }
}

// ---------------- split-bf16 HMMA GEMM, pure-copy operands ----------------
// Scratch arrays referenced DEVICE-SIDE only (host-side __device__-symbol decay reads
// the zero host shadow via ATS — the rounds-4/5/6 bug).
// ASEL 0: A = g_Ah/g_Al slabs; ASEL 1: A = g_Hh/g_Hl slabs. BOFF: offset into g_Bh/g_Bl.
// Grid: (n-tiles, row-tiles) — n-tiles adjacent in schedule so A-slab chunks hit L2.
// 3-stage cp.async pipeline (221184B smem), wait_group 1.
template<int ASEL, int NTOT, int KTOT, int EMODE, int RELU, int BOFF>
__global__ void __launch_bounds__(256, 1)
hmma2(const float* __restrict__ bias, float* __restrict__ Cg)
{
    constexpr int NC  = KTOT / 64;
    constexpr int CB  = 128 * 144;               // smem bytes per component per chunk
    constexpr int CBG = 128 * 128;               // gmem bytes per A-slab chunk (packed)
    constexpr int AHo = 0, ALo = CB, BHo = 2 * CB, BLo = 3 * CB;
    constexpr int STG = 4 * CB;                  // 73728; x3 stages = 221184

    int Meff = g_total;
    int row0 = blockIdx.y * 128;                 // row-tile on Y (grid transposed)
    if (row0 >= Meff) return;
    int n0 = blockIdx.x * 128;                   // n-tile on X (launch-adjacent)
    int rt = blockIdx.y;

    const char* Ahg = (const char*)(ASEL == 0 ? g_Ah : g_Hh);
    const char* Alg = (const char*)(ASEL == 0 ? g_Al : g_Hl);
    const char* Bhg = (const char*)g_Bh + (size_t)BOFF * 2;
    const char* Blg = (const char*)g_Bl + (size_t)BOFF * 2;

    extern __shared__ char dyn[];
    const uint32_t dynb = smem_u32(dyn);
    int tid  = threadIdx.x;
    int wid  = tid >> 5;
    int lane = tid & 31;
    int warp_m = wid & 3;     // 4 x 32 rows
    int warp_n = wid >> 2;    // 2 x 64 cols

    auto cpA = [&](int c, int st) {
        uint32_t dh = dynb + st * STG + AHo;
        uint32_t dl = dynb + st * STG + ALo;
        const char* sh = Ahg + (size_t)(rt * NC + c) * CBG;
        const char* sl = Alg + (size_t)(rt * NC + c) * CBG;
        #pragma unroll
        for (int it = 0; it < 4; it++) {
            int tt = tid + 256 * it;       // 1024 tasks exactly (128 rows x 8 segs)
            int row = tt >> 3, sg = tt & 7;
            uint32_t so  = row * 128 + sg * 16;
            uint32_t dof = row * 144 + sg * 16;
            asm volatile("cp.async.cg.shared.global [%0], [%1], 16;" :: "r"(dh + dof), "l"(sh + so));
            asm volatile("cp.async.cg.shared.global [%0], [%1], 16;" :: "r"(dl + dof), "l"(sl + so));
        }
    };
    auto cpB = [&](int c, int st) {
        uint32_t dh = dynb + st * STG + BHo;
        uint32_t dl = dynb + st * STG + BLo;
        const char* sh = Bhg + ((size_t)c * NTOT + n0) * 144;
        const char* sl = Blg + ((size_t)c * NTOT + n0) * 144;
        #pragma unroll
        for (int it = 0; it < 5; it++) {
            int tt = tid + 256 * it;
            if (tt < 128 * 9) {
                int row = tt / 9, sg = tt - row * 9;
                uint32_t o = row * 144 + sg * 16;
                asm volatile("cp.async.cg.shared.global [%0], [%1], 16;" :: "r"(dh + o), "l"(sh + o));
                asm volatile("cp.async.cg.shared.global [%0], [%1], 16;" :: "r"(dl + o), "l"(sl + o));
            }
        }
    };

    float acc[2][8][4];
    #pragma unroll
    for (int mi = 0; mi < 2; mi++)
        #pragma unroll
        for (int fj = 0; fj < 8; fj++)
            #pragma unroll
            for (int q = 0; q < 4; q++) acc[mi][fj][q] = 0.f;

    uint32_t a_off = (uint32_t)(warp_m * 32 + (lane & 15)) * 144 + ((lane >> 4) << 3) * 2;
    uint32_t b_off = (uint32_t)(warp_n * 64 + (lane & 7) + ((lane >> 4) << 3)) * 144
                   + (((lane >> 3) & 1) << 3) * 2;

    // 3-stage prologue: chunks 0 and 1 in flight
    cpA(0, 0); cpB(0, 0);
    asm volatile("cp.async.commit_group;");
    cpA(1, 1); cpB(1, 1);
    asm volatile("cp.async.commit_group;");
    asm volatile("cp.async.wait_group 1;");     // chunk 0 ready
    __syncthreads();

    for (int c = 0; c < NC; c++) {
        int st = c % 3;
        if (c + 2 < NC) {
            cpA(c + 2, (c + 2) % 3); cpB(c + 2, (c + 2) % 3);
            asm volatile("cp.async.commit_group;");
        }
        uint32_t sb = dynb + st * STG;
        #pragma unroll
        for (int p = 0; p < 3; p++) {
            uint32_t Ab = sb + (p == 2 ? ALo : AHo) + a_off;
            uint32_t Bb = sb + (p == 1 ? BLo : BHo) + b_off;
            #pragma unroll
            for (int k16 = 0; k16 < 4; k16++) {
                uint32_t kb = (uint32_t)k16 * 32;
                uint32_t af[2][4];
                #pragma unroll
                for (int mi = 0; mi < 2; mi++) {
                    uint32_t addr = Ab + mi * 2304 + kb;   // 16 rows * 144B
                    asm volatile("ldmatrix.sync.aligned.m8n8.x4.shared.b16 {%0,%1,%2,%3}, [%4];"
                        : "=r"(af[mi][0]), "=r"(af[mi][1]), "=r"(af[mi][2]), "=r"(af[mi][3])
                        : "r"(addr));
                }
                uint32_t bf[4][4];
                #pragma unroll
                for (int gj = 0; gj < 4; gj++) {
                    uint32_t addr = Bb + gj * 2304 + kb;
                    asm volatile("ldmatrix.sync.aligned.m8n8.x4.shared.b16 {%0,%1,%2,%3}, [%4];"
                        : "=r"(bf[gj][0]), "=r"(bf[gj][1]), "=r"(bf[gj][2]), "=r"(bf[gj][3])
                        : "r"(addr));
                }
                #pragma unroll
                for (int mi = 0; mi < 2; mi++)
                    #pragma unroll
                    for (int gj = 0; gj < 4; gj++) {
                        #pragma unroll
                        for (int h = 0; h < 2; h++) {
                            int fj = gj * 2 + h;
                            asm volatile(
                                "mma.sync.aligned.m16n8k16.row.col.f32.bf16.bf16.f32 "
                                "{%0,%1,%2,%3},{%4,%5,%6,%7},{%8,%9},{%0,%1,%2,%3};"
                                : "+f"(acc[mi][fj][0]), "+f"(acc[mi][fj][1]),
                                  "+f"(acc[mi][fj][2]), "+f"(acc[mi][fj][3])
                                : "r"(af[mi][0]), "r"(af[mi][1]), "r"(af[mi][2]), "r"(af[mi][3]),
                                  "r"(bf[gj][h * 2]), "r"(bf[gj][h * 2 + 1]));
                        }
                    }
            }
        }
        if (c + 1 < NC) {
            if (c + 2 < NC) { asm volatile("cp.async.wait_group 1;"); }
            else            { asm volatile("cp.async.wait_group 0;"); }
            __syncthreads();
        }
    }

    // ---- epilogue ----
    int rl_base = warp_m * 32 + (lane >> 2);
    int cl_base = warp_n * 64 + (lane & 3) * 2;
    if (EMODE == 0) {
        #pragma unroll
        for (int mi = 0; mi < 2; mi++) {
            int r0 = row0 + rl_base + mi * 16;
            #pragma unroll
            for (int fj = 0; fj < 8; fj++) {
                int col = n0 + cl_base + fj * 8;
                float2 bv = *(const float2*)(bias + col);
                float v0 = acc[mi][fj][0] + bv.x;
                float v1 = acc[mi][fj][1] + bv.y;
                float v2 = acc[mi][fj][2] + bv.x;
                float v3 = acc[mi][fj][3] + bv.y;
                if (RELU) { v0 = fmaxf(v0, 0.f); v1 = fmaxf(v1, 0.f); v2 = fmaxf(v2, 0.f); v3 = fmaxf(v3, 0.f); }
                if (r0 < Meff)     *(float2*)(Cg + (size_t)r0 * NTOT + col)       = make_float2(v0, v1);
                if (r0 + 8 < Meff) *(float2*)(Cg + (size_t)(r0 + 8) * NTOT + col) = make_float2(v2, v3);
            }
        }
    } else {
        // split-bf16 H out, PACKED 128-row slabs: ((rt*6 + hc)*128 + row)*64 + kl
        #pragma unroll
        for (int mi = 0; mi < 2; mi++) {
            #pragma unroll
            for (int fj = 0; fj < 8; fj++) {
                int colg = n0 + cl_base + fj * 8;
                int hc = colg >> 6, kl = colg & 63;
                float2 bv = *(const float2*)(bias + colg);
                #pragma unroll
                for (int h2 = 0; h2 < 2; h2++) {
                    int row_l = rl_base + mi * 16 + h2 * 8;
                    float v0 = acc[mi][fj][h2 * 2 + 0] + bv.x;
                    float v1 = acc[mi][fj][h2 * 2 + 1] + bv.y;
                    if (RELU) { v0 = fmaxf(v0, 0.f); v1 = fmaxf(v1, 0.f); }
                    uint32_t hi, lo;
                    split_pair(v0, v1, hi, lo);
                    size_t off = (((size_t)(rt * 6 + hc) * 128 + row_l) * 64 + kl) * 2;
                    *(uint32_t*)((char*)g_Hh + off) = hi;
                    *(uint32_t*)((char*)g_Hl + off) = lo;
                }
            }
        }
    }
}

__global__ void batchout_kernel(float* __restrict__ out, long long out_size)
{
    int t = blockIdx.x * 256 + threadIdx.x;
    int total = g_total;
    if ((long long)total * 257 > out_size) return;
    if (t < total) out[(long long)total * 256 + t] = (float)g_tok_b[t];
}

// ---------------- launch ----------------
extern "C" void kernel_launch(void* const* d_in, const int* in_sizes, int n_in,
                              void* d_out, int out_size)
{
    const float* z     = (const float*)d_in[0];
    const float* kW1   = (const float*)d_in[1];
    const float* kb1   = (const float*)d_in[2];
    const float* kg1   = (const float*)d_in[3];
    const float* kbe1  = (const float*)d_in[4];
    const float* kW2   = (const float*)d_in[5];
    const float* kb2   = (const float*)d_in[6];
    const float* dW1   = (const float*)d_in[7];
    const float* db1   = (const float*)d_in[8];
    const float* dW2   = (const float*)d_in[9];
    const float* db2   = (const float*)d_in[10];
    const float* spW1  = (const float*)d_in[11];
    const float* spb1  = (const float*)d_in[12];
    const float* spg1  = (const float*)d_in[13];
    const float* spbe1 = (const float*)d_in[14];
    const float* spW2  = (const float*)d_in[15];
    const float* spb2  = (const float*)d_in[16];
    float* out = (float*)d_out;

    constexpr int SMEM_HMMA = 3 * 4 * 128 * 144;   // 221184 (3-stage)
    cudaFuncSetAttribute(hmma2<0, DMID, HID, 1, 1, B1_OFF>,
                         cudaFuncAttributeMaxDynamicSharedMemorySize, SMEM_HMMA);
    cudaFuncSetAttribute(hmma2<1, DIM, DMID, 0, 0, B2_OFF>,
                         cudaFuncAttributeMaxDynamicSharedMemorySize, SMEM_HMMA);

    // weight prep
    prep_kernel<B1_OFF><<<(DMID * (HID / 8) + 255) / 256, 256>>>(dW1, HID, DMID);
    prep_kernel<B2_OFF><<<(DIM * (DMID / 8) + 255) / 256, 256>>>(dW2, DMID, DIM);

    // 17 key rows
    keys_kernel<<<dim3(17, 8), 256>>>(kW1, kb1, kg1, kbe1, kW2, kb2);

    // sp GEMM (fp32, bit-exact argmax path — frozen)
    gemm32_sp<<<dim3((KMID + BN - 1) / BN, NB / BM), 128>>>(z, spW1, spb1);

    // size-pred -> g_n -> offsets -> token map
    sizepred_kernel<<<NB / 8, 256>>>(spW2, spb2, spg1, spbe1);
    scan_kernel<<<1, 1024>>>();
    tokmap_kernel<<<NB / 256, 256>>>();

    // pre-split A = z[b]*keys[k]
    gatherA_kernel<<<TMAX * 4 / 256, 256>>>(z);

    // dec1: H = relu(A @ dW1 + b1) -> split-bf16 H slabs   [T x 384]
    // grid: (n-tiles, row-tiles) — n-tiles adjacent for A L2 reuse
    hmma2<0, DMID, HID, 1, 1, B1_OFF>
        <<<dim3(DMID / 128, TMAX / 128), 256, SMEM_HMMA>>>(db1, nullptr);

    // dec2: out = H @ dW2 + b2   [T x 256]
    hmma2<1, DIM, DMID, 0, 0, B2_OFF>
        <<<dim3(DIM / 128, TMAX / 128), 256, SMEM_HMMA>>>(db2, out);

    // optional batch ids
    batchout_kernel<<<TMAX / 256, 256>>>(out, (long long)out_size);
}

// round 9
// speedup vs baseline: 2.7727x; 1.2016x over previous
#include <cuda_runtime.h>
#include <cuda_bf16.h>
#include <cuda_fp16.h>
#include <cstdint>
#include <cstddef>

// Problem constants
#define NB    32768
#define HID   512
#define KMID  264
#define DMID  384
#define DIM   256
#define MAXN  17
#define TMAX  (NB * 16)   // 524288 worst-case tokens

// ---------------- static device scratch ----------------
__device__ __align__(16) float g_keys[MAXN * HID];
__device__ __align__(16) float g_U[(size_t)NB * KMID];
__device__ int   g_n[NB];
__device__ int   g_off[NB];
__device__ int   g_total;
__device__ int   g_tok_b[TMAX];
__device__ unsigned char g_tok_k[TMAX];

// fp16 weights (hi only — B error 2^-11 is within budget): (c*N + n)*72 + kl
#define B1_ELEMS (8 * DMID * 72)
#define B2_ELEMS (6 * DIM * 72)
#define B1_OFF 0
#define B2_OFF B1_ELEMS
__device__ __align__(16) __half g_Bh[B1_ELEMS + B2_ELEMS];

// fp16-split A (z[b]*keys[k]) and H, PACKED 128-row tile slabs (64 elems = 128B/row):
// ((rt*NC + c)*128 + rl)*64 + kl
__device__ __align__(16) __half g_Ah[(size_t)TMAX * 8 * 64];   // 512 MiB
__device__ __align__(16) __half g_Al[(size_t)TMAX * 8 * 64];   // 512 MiB
__device__ __align__(16) __half g_Hh[(size_t)TMAX * 6 * 64];   // 384 MiB
__device__ __align__(16) __half g_Hl[(size_t)TMAX * 6 * 64];   // 384 MiB

__device__ __forceinline__ uint32_t smem_u32(const void* p) {
    uint32_t a;
    asm("{ .reg .u64 t; cvta.to.shared.u64 t, %1; cvt.u32.u64 %0, t; }" : "=r"(a) : "l"(p));
    return a;
}

// fp16 hi/lo split of a float pair (A exact to ~2^-22)
__device__ __forceinline__ void split_pair_h(float a, float b, uint32_t& hi, uint32_t& lo) {
    __half h0 = __float2half_rn(a), h1 = __float2half_rn(b);
    float f0 = __half2float(h0), f1 = __half2float(h1);
    __half l0 = __float2half_rn(a - f0), l1 = __float2half_rn(b - f1);
    hi = (uint32_t)__half_as_ushort(h0) | ((uint32_t)__half_as_ushort(h1) << 16);
    lo = (uint32_t)__half_as_ushort(l0) | ((uint32_t)__half_as_ushort(l1) << 16);
}

// ---------------- weight prep: W[K,N] fp32 -> fp16, [c][n][72] ----------------
template<int BOFF>
__global__ void prep_kernel(const float* __restrict__ W, int K, int N)
{
    int t = blockIdx.x * 256 + threadIdx.x;
    int total = N * (K / 8);
    if (t >= total) return;
    int n  = t / (K / 8);
    int k0 = (t % (K / 8)) * 8;
    unsigned short hb[8];
    #pragma unroll
    for (int j = 0; j < 8; j++)
        hb[j] = __half_as_ushort(__float2half_rn(W[(size_t)(k0 + j) * N + n]));
    uint4 hv;
    hv.x = hb[0] | ((uint32_t)hb[1] << 16); hv.y = hb[2] | ((uint32_t)hb[3] << 16);
    hv.z = hb[4] | ((uint32_t)hb[5] << 16); hv.w = hb[6] | ((uint32_t)hb[7] << 16);
    int c  = k0 / 64;
    int kl = k0 % 64;
    size_t off = ((size_t)BOFF + ((size_t)c * N + n) * 72 + kl) * 2;
    *(uint4*)((char*)g_Bh + off) = hv;
}

// ---------------- keys precompute (17 rows x 8 col-chunks) ----------------
__global__ void keys_kernel(const float* __restrict__ kW1, const float* __restrict__ kb1,
                            const float* __restrict__ kg1, const float* __restrict__ kbe1,
                            const float* __restrict__ kW2, const float* __restrict__ kb2)
{
    int k = blockIdx.x;
    __shared__ float h[KMID];
    __shared__ float red[18];
    int t = threadIdx.x;   // 256
    float s = 0.f, sq = 0.f;
    for (int j = t; j < KMID; j += 256) {
        float u = kW1[k * KMID + j] + kb1[j];
        h[j] = u; s += u; sq += u * u;
    }
    for (int d = 16; d; d >>= 1) { s += __shfl_xor_sync(~0u, s, d); sq += __shfl_xor_sync(~0u, sq, d); }
    if ((t & 31) == 0) { red[t >> 5] = s; red[8 + (t >> 5)] = sq; }
    __syncthreads();
    if (t == 0) {
        float S = 0.f, SQ = 0.f;
        for (int i = 0; i < 8; i++) { S += red[i]; SQ += red[8 + i]; }
        red[16] = S; red[17] = SQ;
    }
    __syncthreads();
    float mean = red[16] * (1.f / KMID);
    float var  = red[17] * (1.f / KMID) - mean * mean;
    float inv  = rsqrtf(var + 1e-5f);
    for (int j = t; j < KMID; j += 256)
        h[j] = fmaxf((h[j] - mean) * inv * kg1[j] + kbe1[j], 0.f);
    __syncthreads();
    if (t < 64) {
        int c = blockIdx.y * 64 + t;
        float acc = kb2[c];
        #pragma unroll 4
        for (int j = 0; j < KMID; j++) acc += h[j] * kW2[(size_t)j * HID + c];
        g_keys[k * HID + c] = acc;
    }
}

// ---------------- fp32 SIMT GEMM for size-pred path (FROZEN: bit-exact argmax safety) ----------------
#define BM 128
#define BN 64
#define BK 16
__global__ void __launch_bounds__(128)
gemm32_sp(const float* __restrict__ Ag, const float* __restrict__ Wg,
          const float* __restrict__ bias)
{
    const int N = KMID, K = HID;
    int row0 = blockIdx.y * BM;
    int col0 = blockIdx.x * BN;

    __shared__ float As[BK][BM];
    __shared__ float Bs[BK][BN];

    int tid = threadIdx.x;
    const float* arow = Ag + (size_t)(row0 + tid) * K;

    float acc[8][8];
    #pragma unroll
    for (int i = 0; i < 8; i++)
        #pragma unroll
        for (int j = 0; j < 8; j++) acc[i][j] = 0.f;

    int tr  = tid & 15;
    int tcg = tid >> 4;

    for (int k0 = 0; k0 < K; k0 += BK) {
        #pragma unroll
        for (int i = 0; i < BK; i += 4) {
            float4 v = *(const float4*)(arow + k0 + i);
            As[i + 0][tid] = v.x; As[i + 1][tid] = v.y;
            As[i + 2][tid] = v.z; As[i + 3][tid] = v.w;
        }
        #pragma unroll
        for (int i = 0; i < 8; i++) {
            int e  = tid + 128 * i;
            int br = e >> 6;
            int bc = e & 63;
            int col = col0 + bc;
            Bs[br][bc] = (col < N) ? Wg[(size_t)(k0 + br) * N + col] : 0.f;
        }
        __syncthreads();
        #pragma unroll
        for (int k = 0; k < BK; k++) {
            float a[8], b[8];
            #pragma unroll
            for (int i = 0; i < 8; i++) a[i] = As[k][tr * 8 + i];
            #pragma unroll
            for (int j = 0; j < 8; j++) b[j] = Bs[k][tcg * 8 + j];
            #pragma unroll
            for (int i = 0; i < 8; i++)
                #pragma unroll
                for (int j = 0; j < 8; j++)
                    acc[i][j] = fmaf(a[i], b[j], acc[i][j]);
        }
        __syncthreads();
    }
    #pragma unroll
    for (int i = 0; i < 8; i++) {
        int row = row0 + tr * 8 + i;
        #pragma unroll
        for (int j = 0; j < 8; j++) {
            int col = col0 + tcg * 8 + j;
            if (col < N) g_U[(size_t)row * N + col] = acc[i][j] + bias[col];
        }
    }
}

// ---------------- size-pred: LN + relu + @sp_W2 + argmax ----------------
__global__ void __launch_bounds__(256)
sizepred_kernel(const float* __restrict__ W2, const float* __restrict__ b2,
                const float* __restrict__ g1, const float* __restrict__ be1)
{
    __shared__ float sW2[KMID * MAXN];
    int tid = threadIdx.x;
    for (int i = tid; i < KMID * MAXN; i += 256) sW2[i] = W2[i];
    __syncthreads();

    int w = blockIdx.x * 8 + (tid >> 5);
    int lane = tid & 31;
    if (w >= NB) return;
    const float* u = g_U + (size_t)w * KMID;
    float vals[9];
    float s = 0.f, sq = 0.f;
    #pragma unroll
    for (int i = 0; i < 9; i++) {
        int j = lane + 32 * i;
        float v = (j < KMID) ? u[j] : 0.f;
        vals[i] = v; s += v; sq += v * v;
    }
    for (int d = 16; d; d >>= 1) { s += __shfl_xor_sync(~0u, s, d); sq += __shfl_xor_sync(~0u, sq, d); }
    float mean = s * (1.f / KMID);
    float var  = sq * (1.f / KMID) - mean * mean;
    float inv  = rsqrtf(var + 1e-5f);
    float logit[MAXN];
    #pragma unroll
    for (int o = 0; o < MAXN; o++) logit[o] = 0.f;
    #pragma unroll
    for (int i = 0; i < 9; i++) {
        int j = lane + 32 * i;
        if (j < KMID) {
            float h = fmaxf((vals[i] - mean) * inv * g1[j] + be1[j], 0.f);
            #pragma unroll
            for (int o = 0; o < MAXN; o++) logit[o] += h * sW2[j * MAXN + o];
        }
    }
    #pragma unroll
    for (int o = 0; o < MAXN; o++)
        for (int d = 16; d; d >>= 1) logit[o] += __shfl_xor_sync(~0u, logit[o], d);
    if (lane == 0) {
        float best = -1e30f; int bi = 0;
        #pragma unroll
        for (int o = 0; o < MAXN; o++) {
            float v = logit[o] + b2[o];
            if (v > best) { best = v; bi = o; }
        }
        g_n[w] = bi;
    }
}

// ---------------- exclusive scan ----------------
__global__ void scan_kernel()
{
    __shared__ int warpsum[32];
    int t = threadIdx.x, l = t & 31, w = t >> 5;
    int base = t * 32;
    int loc[32];
    int s = 0;
    #pragma unroll
    for (int i = 0; i < 32; i++) { loc[i] = s; s += g_n[base + i]; }
    int inc = s;
    #pragma unroll
    for (int d = 1; d < 32; d <<= 1) { int v = __shfl_up_sync(~0u, inc, d); if (l >= d) inc += v; }
    if (l == 31) warpsum[w] = inc;
    __syncthreads();
    if (w == 0) {
        int v = warpsum[l];
        #pragma unroll
        for (int d = 1; d < 32; d <<= 1) { int u2 = __shfl_up_sync(~0u, v, d); if (l >= d) v += u2; }
        warpsum[l] = v;
    }
    __syncthreads();
    int wbase = (w > 0) ? warpsum[w - 1] : 0;
    int exc = wbase + inc - s;
    #pragma unroll
    for (int i = 0; i < 32; i++) g_off[base + i] = exc + loc[i];
    if (t == 1023) g_total = wbase + inc;
}

__global__ void tokmap_kernel()
{
    int b = blockIdx.x * 256 + threadIdx.x;
    if (b >= NB) return;
    int off = g_off[b], n = g_n[b];
    for (int j = 0; j < n; j++) { g_tok_b[off + j] = b; g_tok_k[off + j] = (unsigned char)j; }
}

// ---------------- gatherA: zp = z[b]*keys[k], fp16 hi/lo, PACKED 128-row slabs ----------------
__global__ void gatherA_kernel(const float* __restrict__ z)
{
    int idx = blockIdx.x * 256 + threadIdx.x;
    int T = g_total;
    int rp = (T + 127) & ~127;          // padded rows (tiles fully covered)
    if (idx >= rp * 4) return;
    int row = idx >> 2, q = idx & 3;
    int rc = min(row, T - 1);
    int b  = g_tok_b[rc];
    int kk = g_tok_k[rc];
    const float* zr = z + (size_t)b * HID;
    const float* kr = g_keys + kk * HID;
    int rt = row >> 7, rl = row & 127;
    #pragma unroll
    for (int jj = 0; jj < 16; jj++) {
        int kg = q * 128 + jj * 8;
        float4 a0 = *(const float4*)(zr + kg),     a1 = *(const float4*)(zr + kg + 4);
        float4 k0 = *(const float4*)(kr + kg),     k1 = *(const float4*)(kr + kg + 4);
        float f[8] = { a0.x * k0.x, a0.y * k0.y, a0.z * k0.z, a0.w * k0.w,
                       a1.x * k1.x, a1.y * k1.y, a1.z * k1.z, a1.w * k1.w };
        uint32_t hi[4], lo[4];
        #pragma unroll
        for (int p = 0; p < 4; p++) split_pair_h(f[2 * p], f[2 * p + 1], hi[p], lo[p]);
        int c = kg >> 6, kl = kg & 63;
        size_t off = (((size_t)(rt * 8 + c) * 128 + rl) * 64 + kl) * 2;   // packed: 64 elems/row
        *(uint4*)((char*)g_Ah + off) = make_uint4(hi[0], hi[1], hi[2], hi[3]);
        *(uint4*)((char*)g_Al + off) = make_uint4(lo[0], lo[1], lo[2], lo[3]);
    }
}

// ---------------- 2-pass fp16 HMMA GEMM: D = Ah*Bh + Al*Bh ----------------
// Scratch arrays referenced DEVICE-SIDE only (host-side __device__-symbol decay = ATS
// zero-shadow bug, rounds 4/5/6).
// ASEL 0: A = g_Ah/g_Al; ASEL 1: A = g_Hh/g_Hl. BOFF: offset into g_Bh.
// 3 smem components/stage (Ah, Al, Bh) = 55296B; 4-stage pipeline = 221184B.
template<int ASEL, int NTOT, int KTOT, int EMODE, int RELU, int BOFF>
__global__ void __launch_bounds__(256, 1)
hmma2(const float* __restrict__ bias, float* __restrict__ Cg)
{
    constexpr int NC  = KTOT / 64;
    constexpr int CB  = 128 * 144;               // smem bytes per component per chunk
    constexpr int CBG = 128 * 128;               // gmem bytes per A-slab chunk (packed)
    constexpr int AHo = 0, ALo = CB, BHo = 2 * CB;
    constexpr int STG = 3 * CB;                  // 55296; x4 stages = 221184

    int Meff = g_total;
    int row0 = blockIdx.y * 128;                 // row-tile on Y
    if (row0 >= Meff) return;
    int n0 = blockIdx.x * 128;                   // n-tile on X (launch-adjacent: L2 reuse)
    int rt = blockIdx.y;

    const char* Ahg = (const char*)(ASEL == 0 ? g_Ah : g_Hh);
    const char* Alg = (const char*)(ASEL == 0 ? g_Al : g_Hl);
    const char* Bhg = (const char*)g_Bh + (size_t)BOFF * 2;

    extern __shared__ char dyn[];
    const uint32_t dynb = smem_u32(dyn);
    int tid  = threadIdx.x;
    int wid  = tid >> 5;
    int lane = tid & 31;
    int warp_m = wid & 3;     // 4 x 32 rows
    int warp_n = wid >> 2;    // 2 x 64 cols

    auto cpA = [&](int c, int st) {
        uint32_t dh = dynb + st * STG + AHo;
        uint32_t dl = dynb + st * STG + ALo;
        const char* sh = Ahg + (size_t)(rt * NC + c) * CBG;
        const char* sl = Alg + (size_t)(rt * NC + c) * CBG;
        #pragma unroll
        for (int it = 0; it < 4; it++) {
            int tt = tid + 256 * it;       // 1024 tasks (128 rows x 8 segs)
            int row = tt >> 3, sg = tt & 7;
            uint32_t so  = row * 128 + sg * 16;
            uint32_t dof = row * 144 + sg * 16;
            asm volatile("cp.async.cg.shared.global [%0], [%1], 16;" :: "r"(dh + dof), "l"(sh + so));
            asm volatile("cp.async.cg.shared.global [%0], [%1], 16;" :: "r"(dl + dof), "l"(sl + so));
        }
    };
    auto cpB = [&](int c, int st) {
        uint32_t dh = dynb + st * STG + BHo;
        const char* sh = Bhg + ((size_t)c * NTOT + n0) * 144;
        #pragma unroll
        for (int it = 0; it < 5; it++) {
            int tt = tid + 256 * it;
            if (tt < 128 * 9) {
                int row = tt / 9, sg = tt - row * 9;
                uint32_t o = row * 144 + sg * 16;
                asm volatile("cp.async.cg.shared.global [%0], [%1], 16;" :: "r"(dh + o), "l"(sh + o));
            }
        }
    };

    float acc[2][8][4];
    #pragma unroll
    for (int mi = 0; mi < 2; mi++)
        #pragma unroll
        for (int fj = 0; fj < 8; fj++)
            #pragma unroll
            for (int q = 0; q < 4; q++) acc[mi][fj][q] = 0.f;

    uint32_t a_off = (uint32_t)(warp_m * 32 + (lane & 15)) * 144 + ((lane >> 4) << 3) * 2;
    uint32_t b_off = (uint32_t)(warp_n * 64 + (lane & 7) + ((lane >> 4) << 3)) * 144
                   + (((lane >> 3) & 1) << 3) * 2;

    // 4-stage prologue: chunks 0,1,2 in flight (NC >= 3 always)
    cpA(0, 0); cpB(0, 0);
    asm volatile("cp.async.commit_group;");
    cpA(1, 1); cpB(1, 1);
    asm volatile("cp.async.commit_group;");
    cpA(2, 2); cpB(2, 2);
    asm volatile("cp.async.commit_group;");
    asm volatile("cp.async.wait_group 2;");     // chunk 0 ready
    __syncthreads();

    for (int c = 0; c < NC; c++) {
        int st = c & 3;
        if (c + 3 < NC) {
            cpA(c + 3, (c + 3) & 3); cpB(c + 3, (c + 3) & 3);
            asm volatile("cp.async.commit_group;");
        }
        uint32_t sb = dynb + st * STG;
        #pragma unroll
        for (int p = 0; p < 2; p++) {
            uint32_t Ab = sb + (p ? ALo : AHo) + a_off;
            uint32_t Bb = sb + BHo + b_off;
            #pragma unroll
            for (int k16 = 0; k16 < 4; k16++) {
                uint32_t kb = (uint32_t)k16 * 32;
                uint32_t af[2][4];
                #pragma unroll
                for (int mi = 0; mi < 2; mi++) {
                    uint32_t addr = Ab + mi * 2304 + kb;   // 16 rows * 144B
                    asm volatile("ldmatrix.sync.aligned.m8n8.x4.shared.b16 {%0,%1,%2,%3}, [%4];"
                        : "=r"(af[mi][0]), "=r"(af[mi][1]), "=r"(af[mi][2]), "=r"(af[mi][3])
                        : "r"(addr));
                }
                uint32_t bf[4][4];
                #pragma unroll
                for (int gj = 0; gj < 4; gj++) {
                    uint32_t addr = Bb + gj * 2304 + kb;
                    asm volatile("ldmatrix.sync.aligned.m8n8.x4.shared.b16 {%0,%1,%2,%3}, [%4];"
                        : "=r"(bf[gj][0]), "=r"(bf[gj][1]), "=r"(bf[gj][2]), "=r"(bf[gj][3])
                        : "r"(addr));
                }
                #pragma unroll
                for (int mi = 0; mi < 2; mi++)
                    #pragma unroll
                    for (int gj = 0; gj < 4; gj++) {
                        #pragma unroll
                        for (int h = 0; h < 2; h++) {
                            int fj = gj * 2 + h;
                            asm volatile(
                                "mma.sync.aligned.m16n8k16.row.col.f32.f16.f16.f32 "
                                "{%0,%1,%2,%3},{%4,%5,%6,%7},{%8,%9},{%0,%1,%2,%3};"
                                : "+f"(acc[mi][fj][0]), "+f"(acc[mi][fj][1]),
                                  "+f"(acc[mi][fj][2]), "+f"(acc[mi][fj][3])
                                : "r"(af[mi][0]), "r"(af[mi][1]), "r"(af[mi][2]), "r"(af[mi][3]),
                                  "r"(bf[gj][h * 2]), "r"(bf[gj][h * 2 + 1]));
                        }
                    }
            }
        }
        if (c + 1 < NC) {
            if (c + 4 <= NC)      { asm volatile("cp.async.wait_group 2;"); }
            else if (c + 3 == NC) { asm volatile("cp.async.wait_group 1;"); }
            else                  { asm volatile("cp.async.wait_group 0;"); }
            __syncthreads();
        }
    }

    // ---- epilogue ----
    int rl_base = warp_m * 32 + (lane >> 2);
    int cl_base = warp_n * 64 + (lane & 3) * 2;
    if (EMODE == 0) {
        #pragma unroll
        for (int mi = 0; mi < 2; mi++) {
            int r0 = row0 + rl_base + mi * 16;
            #pragma unroll
            for (int fj = 0; fj < 8; fj++) {
                int col = n0 + cl_base + fj * 8;
                float2 bv = *(const float2*)(bias + col);
                float v0 = acc[mi][fj][0] + bv.x;
                float v1 = acc[mi][fj][1] + bv.y;
                float v2 = acc[mi][fj][2] + bv.x;
                float v3 = acc[mi][fj][3] + bv.y;
                if (RELU) { v0 = fmaxf(v0, 0.f); v1 = fmaxf(v1, 0.f); v2 = fmaxf(v2, 0.f); v3 = fmaxf(v3, 0.f); }
                if (r0 < Meff)     *(float2*)(Cg + (size_t)r0 * NTOT + col)       = make_float2(v0, v1);
                if (r0 + 8 < Meff) *(float2*)(Cg + (size_t)(r0 + 8) * NTOT + col) = make_float2(v2, v3);
            }
        }
    } else {
        // fp16-split H out, PACKED 128-row slabs: ((rt*6 + hc)*128 + row)*64 + kl
        #pragma unroll
        for (int mi = 0; mi < 2; mi++) {
            #pragma unroll
            for (int fj = 0; fj < 8; fj++) {
                int colg = n0 + cl_base + fj * 8;
                int hc = colg >> 6, kl = colg & 63;
                float2 bv = *(const float2*)(bias + colg);
                #pragma unroll
                for (int h2 = 0; h2 < 2; h2++) {
                    int row_l = rl_base + mi * 16 + h2 * 8;
                    float v0 = acc[mi][fj][h2 * 2 + 0] + bv.x;
                    float v1 = acc[mi][fj][h2 * 2 + 1] + bv.y;
                    if (RELU) { v0 = fmaxf(v0, 0.f); v1 = fmaxf(v1, 0.f); }
                    uint32_t hi, lo;
                    split_pair_h(v0, v1, hi, lo);
                    size_t off = (((size_t)(rt * 6 + hc) * 128 + row_l) * 64 + kl) * 2;
                    *(uint32_t*)((char*)g_Hh + off) = hi;
                    *(uint32_t*)((char*)g_Hl + off) = lo;
                }
            }
        }
    }
}

__global__ void batchout_kernel(float* __restrict__ out, long long out_size)
{
    int t = blockIdx.x * 256 + threadIdx.x;
    int total = g_total;
    if ((long long)total * 257 > out_size) return;
    if (t < total) out[(long long)total * 256 + t] = (float)g_tok_b[t];
}

// ---------------- launch ----------------
extern "C" void kernel_launch(void* const* d_in, const int* in_sizes, int n_in,
                              void* d_out, int out_size)
{
    const float* z     = (const float*)d_in[0];
    const float* kW1   = (const float*)d_in[1];
    const float* kb1   = (const float*)d_in[2];
    const float* kg1   = (const float*)d_in[3];
    const float* kbe1  = (const float*)d_in[4];
    const float* kW2   = (const float*)d_in[5];
    const float* kb2   = (const float*)d_in[6];
    const float* dW1   = (const float*)d_in[7];
    const float* db1   = (const float*)d_in[8];
    const float* dW2   = (const float*)d_in[9];
    const float* db2   = (const float*)d_in[10];
    const float* spW1  = (const float*)d_in[11];
    const float* spb1  = (const float*)d_in[12];
    const float* spg1  = (const float*)d_in[13];
    const float* spbe1 = (const float*)d_in[14];
    const float* spW2  = (const float*)d_in[15];
    const float* spb2  = (const float*)d_in[16];
    float* out = (float*)d_out;

    constexpr int SMEM_HMMA = 4 * 3 * 128 * 144;   // 221184 (4-stage, 3 components)
    cudaFuncSetAttribute(hmma2<0, DMID, HID, 1, 1, B1_OFF>,
                         cudaFuncAttributeMaxDynamicSharedMemorySize, SMEM_HMMA);
    cudaFuncSetAttribute(hmma2<1, DIM, DMID, 0, 0, B2_OFF>,
                         cudaFuncAttributeMaxDynamicSharedMemorySize, SMEM_HMMA);

    // weight prep (fp16 hi only)
    prep_kernel<B1_OFF><<<(DMID * (HID / 8) + 255) / 256, 256>>>(dW1, HID, DMID);
    prep_kernel<B2_OFF><<<(DIM * (DMID / 8) + 255) / 256, 256>>>(dW2, DMID, DIM);

    // 17 key rows
    keys_kernel<<<dim3(17, 8), 256>>>(kW1, kb1, kg1, kbe1, kW2, kb2);

    // sp GEMM (fp32, bit-exact argmax path — frozen)
    gemm32_sp<<<dim3((KMID + BN - 1) / BN, NB / BM), 128>>>(z, spW1, spb1);

    // size-pred -> g_n -> offsets -> token map
    sizepred_kernel<<<NB / 8, 256>>>(spW2, spb2, spg1, spbe1);
    scan_kernel<<<1, 1024>>>();
    tokmap_kernel<<<NB / 256, 256>>>();

    // pre-split A = z[b]*keys[k] (fp16 hi/lo)
    gatherA_kernel<<<TMAX * 4 / 256, 256>>>(z);

    // dec1: H = relu(A @ dW1 + b1) -> fp16-split H slabs   [T x 384]
    hmma2<0, DMID, HID, 1, 1, B1_OFF>
        <<<dim3(DMID / 128, TMAX / 128), 256, SMEM_HMMA>>>(db1, nullptr);

    // dec2: out = H @ dW2 + b2   [T x 256]
    hmma2<1, DIM, DMID, 0, 0, B2_OFF>
        <<<dim3(DIM / 128, TMAX / 128), 256, SMEM_HMMA>>>(db2, out);

    // optional batch ids
    batchout_kernel<<<TMAX / 256, 256>>>(out, (long long)out_size);
}